// round 1
// baseline (speedup 1.0000x reference)
#include <cuda_runtime.h>
#include <math.h>

// Problem constants
#define BB 4
#define NN 2048
#define EE 768
#define HH 8
#define DD 96
#define SCALING 0.1020620726159658f   // 96^-0.5

// Scratch (static device globals; no allocation)
__device__ float g_Q[BB * HH * NN * DD];   // [b][h][n][d]
__device__ float g_K[BB * HH * NN * DD];
__device__ float g_V[BB * HH * NN * DD];
__device__ float g_ctx[BB * NN * EE];      // [b][n][e]

// ---------------------------------------------------------------------------
// Kernel 1: QKV projection. x[8192,768] @ Wqkv[768,2304] + bqkv -> scatter
// into Q/K/V laid out [B,H,N,D]. Column c of Wqkv maps to
// sel=c%3 (0=Q,1=K,2=V), hd=c/3, h=hd/96, d=hd%96.
// ---------------------------------------------------------------------------
__global__ __launch_bounds__(256) void qkv_gemm_kernel(
    const float* __restrict__ A,      // x, [8192,768]
    const float* __restrict__ W,      // Wqkv, [768,2304]
    const float* __restrict__ bias)   // bqkv, [2304]
{
    __shared__ float As[16][65];
    __shared__ float Bs[16][64];

    const int tid = threadIdx.x;
    const int tx  = tid & 15;
    const int ty  = tid >> 4;
    const int row0 = blockIdx.y * 64;
    const int col0 = blockIdx.x * 64;

    float acc[4][4] = {};

    for (int kt = 0; kt < 768; kt += 16) {
        // load A tile 64x16
        #pragma unroll
        for (int p = 0; p < 4; p++) {
            int r = (tid >> 4) + p * 16;
            int k = tid & 15;
            As[k][r] = A[(row0 + r) * 768 + kt + k];
        }
        // load B tile 16x64
        #pragma unroll
        for (int p = 0; p < 4; p++) {
            int k = (tid >> 6) + p * 4;
            int c = tid & 63;
            Bs[k][c] = W[(kt + k) * 2304 + col0 + c];
        }
        __syncthreads();

        #pragma unroll
        for (int k = 0; k < 16; k++) {
            float a[4], b[4];
            #pragma unroll
            for (int r = 0; r < 4; r++) a[r] = As[k][ty * 4 + r];
            #pragma unroll
            for (int c = 0; c < 4; c++) b[c] = Bs[k][tx + 16 * c];
            #pragma unroll
            for (int r = 0; r < 4; r++)
                #pragma unroll
                for (int c = 0; c < 4; c++)
                    acc[r][c] = fmaf(a[r], b[c], acc[r][c]);
        }
        __syncthreads();
    }

    #pragma unroll
    for (int r = 0; r < 4; r++) {
        int m = row0 + ty * 4 + r;
        int b = m >> 11;          // /2048
        int n = m & 2047;
        #pragma unroll
        for (int c = 0; c < 4; c++) {
            int cc  = col0 + tx + 16 * c;
            int sel = cc % 3;
            int hd  = cc / 3;
            int h   = hd / 96;
            int d   = hd % 96;
            float v = acc[r][c] + bias[cc];
            int o = ((b * HH + h) * NN + n) * DD + d;
            if (sel == 0)      g_Q[o] = v;
            else if (sel == 1) g_K[o] = v;
            else               g_V[o] = v;
        }
    }
}

// ---------------------------------------------------------------------------
// Kernel 2: flash attention, fp32. One (b,h, q-tile of 32) per block.
// BN=64 keys per iteration. Softmax WITHOUT pre-scaling; SCALING applied
// after normalization (matches reference). Writes ctx in [B,N,E] layout.
// ---------------------------------------------------------------------------
__global__ __launch_bounds__(256) void attn_kernel()
{
    __shared__ float Qs[32][96];     // broadcast reads, no pad needed
    __shared__ float KVs[64][97];    // shared K/V buffer, padded
    __shared__ float Ps[32][65];     // P tile, padded

    const int tid = threadIdx.x;
    const int lane = tid & 31;       // tx
    const int wid  = tid >> 5;       // ty: 8 warps, 4 query rows each
    const int q0   = blockIdx.x * 32;
    const int bh   = blockIdx.y;     // b*H + h
    const int b    = bh >> 3;
    const int h    = bh & 7;

    const float* Qg = g_Q + (size_t)bh * NN * DD;
    const float* Kg = g_K + (size_t)bh * NN * DD;
    const float* Vg = g_V + (size_t)bh * NN * DD;

    // load Q tile 32x96 (3072 floats, 12 per thread)
    #pragma unroll
    for (int p = 0; p < 12; p++) {
        int idx = tid + p * 256;
        int r = idx / 96, d = idx % 96;
        Qs[r][d] = Qg[(q0 + r) * DD + d];
    }

    float m_r[4], l_r[4], acc[4][3];
    #pragma unroll
    for (int r = 0; r < 4; r++) {
        m_r[r] = -1e30f; l_r[r] = 0.f;
        acc[r][0] = acc[r][1] = acc[r][2] = 0.f;
    }

    for (int t = 0; t < NN / 64; t++) {
        const int j0 = t * 64;
        __syncthreads();
        // load K tile 64x96 (24 per thread)
        #pragma unroll
        for (int p = 0; p < 24; p++) {
            int idx = tid + p * 256;
            int r = idx / 96, d = idx % 96;
            KVs[r][d] = Kg[(j0 + r) * DD + d];
        }
        __syncthreads();

        // S = Q K^T : each thread -> 4 rows x 2 cols (cols lane, lane+32)
        float s[4][2] = {};
        #pragma unroll 4
        for (int d = 0; d < 96; d++) {
            float k0 = KVs[lane][d];
            float k1 = KVs[lane + 32][d];
            #pragma unroll
            for (int r = 0; r < 4; r++) {
                float q = Qs[wid * 4 + r][d];
                s[r][0] = fmaf(q, k0, s[r][0]);
                s[r][1] = fmaf(q, k1, s[r][1]);
            }
        }

        // online softmax update
        #pragma unroll
        for (int r = 0; r < 4; r++) {
            float tmax = fmaxf(s[r][0], s[r][1]);
            #pragma unroll
            for (int off = 16; off > 0; off >>= 1)
                tmax = fmaxf(tmax, __shfl_xor_sync(0xffffffffu, tmax, off));
            float mnew  = fmaxf(m_r[r], tmax);
            float scale = __expf(m_r[r] - mnew);
            float p0 = __expf(s[r][0] - mnew);
            float p1 = __expf(s[r][1] - mnew);
            float rs = p0 + p1;
            #pragma unroll
            for (int off = 16; off > 0; off >>= 1)
                rs += __shfl_xor_sync(0xffffffffu, rs, off);
            l_r[r] = l_r[r] * scale + rs;
            m_r[r] = mnew;
            acc[r][0] *= scale; acc[r][1] *= scale; acc[r][2] *= scale;
            Ps[wid * 4 + r][lane]      = p0;
            Ps[wid * 4 + r][lane + 32] = p1;
        }

        __syncthreads();   // Ps visible; KVs free to overwrite
        // load V tile 64x96
        #pragma unroll
        for (int p = 0; p < 24; p++) {
            int idx = tid + p * 256;
            int r = idx / 96, d = idx % 96;
            KVs[r][d] = Vg[(j0 + r) * DD + d];
        }
        __syncthreads();

        // acc += P @ V
        #pragma unroll 2
        for (int j = 0; j < 64; j++) {
            float v0 = KVs[j][lane];
            float v1 = KVs[j][lane + 32];
            float v2 = KVs[j][lane + 64];
            #pragma unroll
            for (int r = 0; r < 4; r++) {
                float p = Ps[wid * 4 + r][j];
                acc[r][0] = fmaf(p, v0, acc[r][0]);
                acc[r][1] = fmaf(p, v1, acc[r][1]);
                acc[r][2] = fmaf(p, v2, acc[r][2]);
            }
        }
    }

    // epilogue: out = (acc / l) * SCALING  -> ctx[b][n][h*96 + e]
    #pragma unroll
    for (int r = 0; r < 4; r++) {
        float inv = SCALING / l_r[r];
        int n = q0 + wid * 4 + r;
        float* dst = g_ctx + ((size_t)b * NN + n) * EE + h * DD;
        dst[lane]      = acc[r][0] * inv;
        dst[lane + 32] = acc[r][1] * inv;
        dst[lane + 64] = acc[r][2] * inv;
    }
}

// ---------------------------------------------------------------------------
// Kernel 3: output projection. ctx[8192,768] @ Wproj[768,768] + bproj -> out
// ---------------------------------------------------------------------------
__global__ __launch_bounds__(256) void proj_gemm_kernel(
    const float* __restrict__ W,      // Wproj, [768,768]
    const float* __restrict__ bias,   // bproj, [768]
    float* __restrict__ out)          // [8192,768]
{
    __shared__ float As[16][65];
    __shared__ float Bs[16][64];

    const int tid = threadIdx.x;
    const int tx  = tid & 15;
    const int ty  = tid >> 4;
    const int row0 = blockIdx.y * 64;
    const int col0 = blockIdx.x * 64;

    float acc[4][4] = {};

    for (int kt = 0; kt < 768; kt += 16) {
        #pragma unroll
        for (int p = 0; p < 4; p++) {
            int r = (tid >> 4) + p * 16;
            int k = tid & 15;
            As[k][r] = g_ctx[(size_t)(row0 + r) * 768 + kt + k];
        }
        #pragma unroll
        for (int p = 0; p < 4; p++) {
            int k = (tid >> 6) + p * 4;
            int c = tid & 63;
            Bs[k][c] = W[(kt + k) * 768 + col0 + c];
        }
        __syncthreads();

        #pragma unroll
        for (int k = 0; k < 16; k++) {
            float a[4], b[4];
            #pragma unroll
            for (int r = 0; r < 4; r++) a[r] = As[k][ty * 4 + r];
            #pragma unroll
            for (int c = 0; c < 4; c++) b[c] = Bs[k][tx + 16 * c];
            #pragma unroll
            for (int r = 0; r < 4; r++)
                #pragma unroll
                for (int c = 0; c < 4; c++)
                    acc[r][c] = fmaf(a[r], b[c], acc[r][c]);
        }
        __syncthreads();
    }

    #pragma unroll
    for (int r = 0; r < 4; r++) {
        int m = row0 + ty * 4 + r;
        #pragma unroll
        for (int c = 0; c < 4; c++) {
            int cc = col0 + tx + 16 * c;
            out[(size_t)m * 768 + cc] = acc[r][c] + bias[cc];
        }
    }
}

// ---------------------------------------------------------------------------
extern "C" void kernel_launch(void* const* d_in, const int* in_sizes, int n_in,
                              void* d_out, int out_size)
{
    const float* x     = (const float*)d_in[0];
    const float* Wqkv  = (const float*)d_in[1];
    const float* bqkv  = (const float*)d_in[2];
    const float* Wproj = (const float*)d_in[3];
    const float* bproj = (const float*)d_in[4];
    float* out = (float*)d_out;

    dim3 g1(2304 / 64, (BB * NN) / 64);   // 36 x 128
    qkv_gemm_kernel<<<g1, 256>>>(x, Wqkv, bqkv);

    dim3 g2(NN / 32, BB * HH);            // 64 x 32
    attn_kernel<<<g2, 256>>>();

    dim3 g3(768 / 64, (BB * NN) / 64);    // 12 x 128
    proj_gemm_kernel<<<g3, 256>>>(Wproj, bproj, out);
}

// round 5
// speedup vs baseline: 1.2750x; 1.2750x over previous
#include <cuda_runtime.h>
#include <cstdint>
#include <math.h>

// Problem constants
#define BB 4
#define NN 2048
#define EE 768
#define HH 8
#define DD 96
#define SCALING 0.1020620726159658f   // 96^-0.5

// Scratch (static device globals; no allocation)
__device__ float g_Q[BB * HH * NN * DD];   // [b][h][n][d]
__device__ float g_K[BB * HH * NN * DD];
__device__ float g_V[BB * HH * NN * DD];
__device__ float g_ctx[BB * NN * EE];      // [b][n][e]

// ---------------------------------------------------------------------------
// tf32 helpers (legacy mma.sync path — supported on compute_103 PTX target)
// ---------------------------------------------------------------------------
__device__ __forceinline__ uint32_t tf32r(float x) {
    uint32_t y;
    asm("cvt.rna.tf32.f32 %0, %1;" : "=r"(y) : "f"(x));
    return y;
}

__device__ __forceinline__ void mma_tf32(float* c, const uint32_t* a,
                                         const uint32_t* b) {
    asm volatile(
        "mma.sync.aligned.m16n8k8.row.col.f32.tf32.tf32.f32 "
        "{%0,%1,%2,%3}, {%4,%5,%6,%7}, {%8,%9}, {%0,%1,%2,%3};\n"
        : "+f"(c[0]), "+f"(c[1]), "+f"(c[2]), "+f"(c[3])
        : "r"(a[0]), "r"(a[1]), "r"(a[2]), "r"(a[3]), "r"(b[0]), "r"(b[1]));
}

// ---------------------------------------------------------------------------
// Tensor-core tf32 GEMM: C[8192, LDW] = A[8192,768] @ W[768,LDW] + bias
// Block tile 128x128x32, 8 warps (4x2), warp tile 32x64 = 2x8 m16n8k8 frags.
// smem: A [128][36] row-major, B [32][136] row-major (pads -> conflict-free).
// Fragment coordinates per PTX ISA / CUTLASS SM80_16x8x8_F32TF32TF32F32_TN:
//   A: a0=(g,t) a1=(g+8,t) a2=(g,t+4) a3=(g+8,t+4)   g=lane>>2, t=lane&3
//   B: b0=(k=t, n=g)  b1=(k=t+4, n=g)
//   C: c0=(g,2t) c1=(g,2t+1) c2=(g+8,2t) c3=(g+8,2t+1)
// MODE 0: A = g_ctx (resolved IN DEVICE CODE), write `out` (proj).
// MODE 1: A = arg (x), scatter into g_Q/g_K/g_V (qkv).
// ---------------------------------------------------------------------------
#define APAD 36
#define BPAD 136

template<int MODE, int LDW>
__global__ __launch_bounds__(256) void gemm_mma(
    const float* __restrict__ Aarg,
    const float* __restrict__ W,
    const float* __restrict__ bias,
    float* __restrict__ out)
{
    __shared__ uint32_t sA[128 * APAD];   // 18 KB
    __shared__ uint32_t sB[32 * BPAD];    // 17 KB

    // CRITICAL: device symbols must be resolved in device code, not host.
    const float* A = (MODE == 0) ? (const float*)g_ctx : Aarg;

    const int tid  = threadIdx.x;
    const int lane = tid & 31;
    const int wid  = tid >> 5;
    const int wm   = wid & 3;       // warp row 0..3  (m offset wm*32)
    const int wn   = wid >> 2;      // warp col 0..1  (n offset wn*64)
    const int row0 = blockIdx.y * 128;
    const int col0 = blockIdx.x * 128;
    const int g    = lane >> 2;
    const int t    = lane & 3;

    float acc[2][8][4];
    #pragma unroll
    for (int ml = 0; ml < 2; ml++)
        #pragma unroll
        for (int nl = 0; nl < 8; nl++)
            #pragma unroll
            for (int e = 0; e < 4; e++) acc[ml][nl][e] = 0.f;

    uint32_t stA[4][4], stB[4][4];

    // ---- ldg chunk kt into stage regs (coalesced float4) ----
    auto ldg_chunk = [&](int kt) {
        #pragma unroll
        for (int p = 0; p < 4; p++) {
            int i  = tid + p * 256;
            int m  = i >> 3, k4 = i & 7;          // 128 rows x 8 float4
            float4 v = *(const float4*)(A + (size_t)(row0 + m) * 768 + kt * 32 + k4 * 4);
            stA[p][0] = tf32r(v.x); stA[p][1] = tf32r(v.y);
            stA[p][2] = tf32r(v.z); stA[p][3] = tf32r(v.w);
        }
        #pragma unroll
        for (int p = 0; p < 4; p++) {
            int i  = tid + p * 256;
            int k  = i >> 5, n4 = i & 31;         // 32 rows x 32 float4
            float4 v = *(const float4*)(W + (size_t)(kt * 32 + k) * LDW + col0 + n4 * 4);
            stB[p][0] = tf32r(v.x); stB[p][1] = tf32r(v.y);
            stB[p][2] = tf32r(v.z); stB[p][3] = tf32r(v.w);
        }
    };

    // ---- store stage regs into smem (A: [m][k] pad 36, B: [k][n] pad 136) --
    auto sts_chunk = [&]() {
        #pragma unroll
        for (int p = 0; p < 4; p++) {
            int i  = tid + p * 256;
            int m  = i >> 3, k4 = i & 7;
            *(uint4*)&sA[m * APAD + k4 * 4] =
                make_uint4(stA[p][0], stA[p][1], stA[p][2], stA[p][3]);
        }
        #pragma unroll
        for (int p = 0; p < 4; p++) {
            int i  = tid + p * 256;
            int k  = i >> 5, n4 = i & 31;
            *(uint4*)&sB[k * BPAD + n4 * 4] =
                make_uint4(stB[p][0], stB[p][1], stB[p][2], stB[p][3]);
        }
    };

    ldg_chunk(0);

    #pragma unroll 1
    for (int kt = 0; kt < 24; kt++) {
        sts_chunk();
        __syncthreads();
        if (kt < 23) ldg_chunk(kt + 1);   // next-chunk LDG hidden under MMA

        #pragma unroll
        for (int ks = 0; ks < 4; ks++) {
            const int k0 = ks * 8;
            uint32_t af[2][4];
            #pragma unroll
            for (int ml = 0; ml < 2; ml++) {
                const int m_off = wm * 32 + ml * 16;
                af[ml][0] = sA[(m_off + g)     * APAD + k0 + t];
                af[ml][1] = sA[(m_off + g + 8) * APAD + k0 + t];
                af[ml][2] = sA[(m_off + g)     * APAD + k0 + t + 4];
                af[ml][3] = sA[(m_off + g + 8) * APAD + k0 + t + 4];
            }
            #pragma unroll
            for (int nl = 0; nl < 8; nl++) {
                const int n_off = wn * 64 + nl * 8;
                uint32_t bf[2];
                bf[0] = sB[(k0 + t)     * BPAD + n_off + g];
                bf[1] = sB[(k0 + t + 4) * BPAD + n_off + g];
                mma_tf32(acc[0][nl], af[0], bf);
                mma_tf32(acc[1][nl], af[1], bf);
            }
        }
        __syncthreads();
    }

    // ---- epilogue ----
    if (MODE == 0) {
        #pragma unroll
        for (int ml = 0; ml < 2; ml++) {
            #pragma unroll
            for (int rh = 0; rh < 2; rh++) {
                int m = row0 + wm * 32 + ml * 16 + g + rh * 8;
                float* op = out + (size_t)m * LDW;
                #pragma unroll
                for (int nl = 0; nl < 8; nl++) {
                    int c = col0 + wn * 64 + nl * 8 + 2 * t;
                    float2 bv = *(const float2*)(bias + c);
                    float2 o;
                    o.x = acc[ml][nl][rh * 2 + 0] + bv.x;
                    o.y = acc[ml][nl][rh * 2 + 1] + bv.y;
                    *(float2*)(op + c) = o;
                }
            }
        }
    } else {
        #pragma unroll
        for (int ml = 0; ml < 2; ml++) {
            #pragma unroll
            for (int rh = 0; rh < 2; rh++) {
                int m = row0 + wm * 32 + ml * 16 + g + rh * 8;
                int b = m >> 11, n = m & 2047;
                #pragma unroll
                for (int nl = 0; nl < 8; nl++) {
                    #pragma unroll
                    for (int e = 0; e < 2; e++) {
                        int c = col0 + wn * 64 + nl * 8 + 2 * t + e;
                        float v = acc[ml][nl][rh * 2 + e] + __ldg(bias + c);
                        int sel = c % 3;
                        int hd  = c / 3;
                        int h   = hd / 96;
                        int d   = hd - h * 96;
                        size_t o = ((size_t)(b * HH + h) * NN + n) * DD + d;
                        if (sel == 0)      g_Q[o] = v;
                        else if (sel == 1) g_K[o] = v;
                        else               g_V[o] = v;
                    }
                }
            }
        }
    }
}

// ---------------------------------------------------------------------------
// Kernel 2: flash attention, fp32 (unchanged; validated R1).
// ---------------------------------------------------------------------------
__global__ __launch_bounds__(256) void attn_kernel()
{
    __shared__ float Qs[32][96];
    __shared__ float KVs[64][97];
    __shared__ float Ps[32][65];

    const int tid = threadIdx.x;
    const int lane = tid & 31;
    const int wid  = tid >> 5;
    const int q0   = blockIdx.x * 32;
    const int bh   = blockIdx.y;
    const int b    = bh >> 3;
    const int h    = bh & 7;

    const float* Qg = g_Q + (size_t)bh * NN * DD;
    const float* Kg = g_K + (size_t)bh * NN * DD;
    const float* Vg = g_V + (size_t)bh * NN * DD;

    #pragma unroll
    for (int p = 0; p < 12; p++) {
        int idx = tid + p * 256;
        int r = idx / 96, d = idx % 96;
        Qs[r][d] = Qg[(q0 + r) * DD + d];
    }

    float m_r[4], l_r[4], acc[4][3];
    #pragma unroll
    for (int r = 0; r < 4; r++) {
        m_r[r] = -1e30f; l_r[r] = 0.f;
        acc[r][0] = acc[r][1] = acc[r][2] = 0.f;
    }

    for (int tt = 0; tt < NN / 64; tt++) {
        const int j0 = tt * 64;
        __syncthreads();
        #pragma unroll
        for (int p = 0; p < 24; p++) {
            int idx = tid + p * 256;
            int r = idx / 96, d = idx % 96;
            KVs[r][d] = Kg[(j0 + r) * DD + d];
        }
        __syncthreads();

        float s[4][2] = {};
        #pragma unroll 4
        for (int d = 0; d < 96; d++) {
            float k0 = KVs[lane][d];
            float k1 = KVs[lane + 32][d];
            #pragma unroll
            for (int r = 0; r < 4; r++) {
                float q = Qs[wid * 4 + r][d];
                s[r][0] = fmaf(q, k0, s[r][0]);
                s[r][1] = fmaf(q, k1, s[r][1]);
            }
        }

        #pragma unroll
        for (int r = 0; r < 4; r++) {
            float tmax = fmaxf(s[r][0], s[r][1]);
            #pragma unroll
            for (int off = 16; off > 0; off >>= 1)
                tmax = fmaxf(tmax, __shfl_xor_sync(0xffffffffu, tmax, off));
            float mnew  = fmaxf(m_r[r], tmax);
            float scale = __expf(m_r[r] - mnew);
            float p0 = __expf(s[r][0] - mnew);
            float p1 = __expf(s[r][1] - mnew);
            float rs = p0 + p1;
            #pragma unroll
            for (int off = 16; off > 0; off >>= 1)
                rs += __shfl_xor_sync(0xffffffffu, rs, off);
            l_r[r] = l_r[r] * scale + rs;
            m_r[r] = mnew;
            acc[r][0] *= scale; acc[r][1] *= scale; acc[r][2] *= scale;
            Ps[wid * 4 + r][lane]      = p0;
            Ps[wid * 4 + r][lane + 32] = p1;
        }

        __syncthreads();
        #pragma unroll
        for (int p = 0; p < 24; p++) {
            int idx = tid + p * 256;
            int r = idx / 96, d = idx % 96;
            KVs[r][d] = Vg[(j0 + r) * DD + d];
        }
        __syncthreads();

        #pragma unroll 2
        for (int j = 0; j < 64; j++) {
            float v0 = KVs[j][lane];
            float v1 = KVs[j][lane + 32];
            float v2 = KVs[j][lane + 64];
            #pragma unroll
            for (int r = 0; r < 4; r++) {
                float p = Ps[wid * 4 + r][j];
                acc[r][0] = fmaf(p, v0, acc[r][0]);
                acc[r][1] = fmaf(p, v1, acc[r][1]);
                acc[r][2] = fmaf(p, v2, acc[r][2]);
            }
        }
    }

    #pragma unroll
    for (int r = 0; r < 4; r++) {
        float inv = SCALING / l_r[r];
        int n = q0 + wid * 4 + r;
        float* dst = g_ctx + ((size_t)b * NN + n) * EE + h * DD;
        dst[lane]      = acc[r][0] * inv;
        dst[lane + 32] = acc[r][1] * inv;
        dst[lane + 64] = acc[r][2] * inv;
    }
}

// ---------------------------------------------------------------------------
extern "C" void kernel_launch(void* const* d_in, const int* in_sizes, int n_in,
                              void* d_out, int out_size)
{
    const float* x     = (const float*)d_in[0];
    const float* Wqkv  = (const float*)d_in[1];
    const float* bqkv  = (const float*)d_in[2];
    const float* Wproj = (const float*)d_in[3];
    const float* bproj = (const float*)d_in[4];
    float* out = (float*)d_out;

    dim3 g1(2304 / 128, 8192 / 128);      // 18 x 64
    gemm_mma<1, 2304><<<g1, 256>>>(x, Wqkv, bqkv, nullptr);

    dim3 g2(NN / 32, BB * HH);            // 64 x 32
    attn_kernel<<<g2, 256>>>();

    dim3 g3(768 / 128, 8192 / 128);       // 6 x 64
    gemm_mma<0, 768><<<g3, 256>>>(nullptr, Wproj, bproj, out);
}

// round 6
// speedup vs baseline: 2.8416x; 2.2287x over previous
#include <cuda_runtime.h>
#include <cstdint>
#include <math.h>

// Problem constants
#define BB 4
#define NN 2048
#define EE 768
#define HH 8
#define DD 96
#define SCALING 0.1020620726159658f   // 96^-0.5

// Scratch (static device globals; no allocation)
__device__ float g_Q[BB * HH * NN * DD];   // [b][h][n][d]
__device__ float g_K[BB * HH * NN * DD];
__device__ float g_V[BB * HH * NN * DD];
__device__ float g_ctx[BB * NN * EE];      // [b][n][e]

// ---------------------------------------------------------------------------
// tf32 helpers (legacy mma.sync path — supported on compute_103 PTX target)
// ---------------------------------------------------------------------------
__device__ __forceinline__ uint32_t tf32r(float x) {
    uint32_t y;
    asm("cvt.rna.tf32.f32 %0, %1;" : "=r"(y) : "f"(x));
    return y;
}

__device__ __forceinline__ void mma_tf32(float* c, const uint32_t* a,
                                         const uint32_t* b) {
    asm volatile(
        "mma.sync.aligned.m16n8k8.row.col.f32.tf32.tf32.f32 "
        "{%0,%1,%2,%3}, {%4,%5,%6,%7}, {%8,%9}, {%0,%1,%2,%3};\n"
        : "+f"(c[0]), "+f"(c[1]), "+f"(c[2]), "+f"(c[3])
        : "r"(a[0]), "r"(a[1]), "r"(a[2]), "r"(a[3]), "r"(b[0]), "r"(b[1]));
}

// ---------------------------------------------------------------------------
// Tensor-core tf32 GEMM (validated R5): C[8192,LDW] = A[8192,768] @ W + bias
// ---------------------------------------------------------------------------
#define APAD 36
#define BPAD 136

template<int MODE, int LDW>
__global__ __launch_bounds__(256) void gemm_mma(
    const float* __restrict__ Aarg,
    const float* __restrict__ W,
    const float* __restrict__ bias,
    float* __restrict__ out)
{
    __shared__ uint32_t sA[128 * APAD];   // 18 KB
    __shared__ uint32_t sB[32 * BPAD];    // 17 KB

    // device symbols must be resolved in device code, not host
    const float* A = (MODE == 0) ? (const float*)g_ctx : Aarg;

    const int tid  = threadIdx.x;
    const int lane = tid & 31;
    const int wid  = tid >> 5;
    const int wm   = wid & 3;
    const int wn   = wid >> 2;
    const int row0 = blockIdx.y * 128;
    const int col0 = blockIdx.x * 128;
    const int g    = lane >> 2;
    const int t    = lane & 3;

    float acc[2][8][4];
    #pragma unroll
    for (int ml = 0; ml < 2; ml++)
        #pragma unroll
        for (int nl = 0; nl < 8; nl++)
            #pragma unroll
            for (int e = 0; e < 4; e++) acc[ml][nl][e] = 0.f;

    uint32_t stA[4][4], stB[4][4];

    auto ldg_chunk = [&](int kt) {
        #pragma unroll
        for (int p = 0; p < 4; p++) {
            int i  = tid + p * 256;
            int m  = i >> 3, k4 = i & 7;
            float4 v = *(const float4*)(A + (size_t)(row0 + m) * 768 + kt * 32 + k4 * 4);
            stA[p][0] = tf32r(v.x); stA[p][1] = tf32r(v.y);
            stA[p][2] = tf32r(v.z); stA[p][3] = tf32r(v.w);
        }
        #pragma unroll
        for (int p = 0; p < 4; p++) {
            int i  = tid + p * 256;
            int k  = i >> 5, n4 = i & 31;
            float4 v = *(const float4*)(W + (size_t)(kt * 32 + k) * LDW + col0 + n4 * 4);
            stB[p][0] = tf32r(v.x); stB[p][1] = tf32r(v.y);
            stB[p][2] = tf32r(v.z); stB[p][3] = tf32r(v.w);
        }
    };

    auto sts_chunk = [&]() {
        #pragma unroll
        for (int p = 0; p < 4; p++) {
            int i  = tid + p * 256;
            int m  = i >> 3, k4 = i & 7;
            *(uint4*)&sA[m * APAD + k4 * 4] =
                make_uint4(stA[p][0], stA[p][1], stA[p][2], stA[p][3]);
        }
        #pragma unroll
        for (int p = 0; p < 4; p++) {
            int i  = tid + p * 256;
            int k  = i >> 5, n4 = i & 31;
            *(uint4*)&sB[k * BPAD + n4 * 4] =
                make_uint4(stB[p][0], stB[p][1], stB[p][2], stB[p][3]);
        }
    };

    ldg_chunk(0);

    #pragma unroll 1
    for (int kt = 0; kt < 24; kt++) {
        sts_chunk();
        __syncthreads();
        if (kt < 23) ldg_chunk(kt + 1);

        #pragma unroll
        for (int ks = 0; ks < 4; ks++) {
            const int k0 = ks * 8;
            uint32_t af[2][4];
            #pragma unroll
            for (int ml = 0; ml < 2; ml++) {
                const int m_off = wm * 32 + ml * 16;
                af[ml][0] = sA[(m_off + g)     * APAD + k0 + t];
                af[ml][1] = sA[(m_off + g + 8) * APAD + k0 + t];
                af[ml][2] = sA[(m_off + g)     * APAD + k0 + t + 4];
                af[ml][3] = sA[(m_off + g + 8) * APAD + k0 + t + 4];
            }
            #pragma unroll
            for (int nl = 0; nl < 8; nl++) {
                const int n_off = wn * 64 + nl * 8;
                uint32_t bf[2];
                bf[0] = sB[(k0 + t)     * BPAD + n_off + g];
                bf[1] = sB[(k0 + t + 4) * BPAD + n_off + g];
                mma_tf32(acc[0][nl], af[0], bf);
                mma_tf32(acc[1][nl], af[1], bf);
            }
        }
        __syncthreads();
    }

    if (MODE == 0) {
        #pragma unroll
        for (int ml = 0; ml < 2; ml++) {
            #pragma unroll
            for (int rh = 0; rh < 2; rh++) {
                int m = row0 + wm * 32 + ml * 16 + g + rh * 8;
                float* op = out + (size_t)m * LDW;
                #pragma unroll
                for (int nl = 0; nl < 8; nl++) {
                    int c = col0 + wn * 64 + nl * 8 + 2 * t;
                    float2 bv = *(const float2*)(bias + c);
                    float2 o;
                    o.x = acc[ml][nl][rh * 2 + 0] + bv.x;
                    o.y = acc[ml][nl][rh * 2 + 1] + bv.y;
                    *(float2*)(op + c) = o;
                }
            }
        }
    } else {
        #pragma unroll
        for (int ml = 0; ml < 2; ml++) {
            #pragma unroll
            for (int rh = 0; rh < 2; rh++) {
                int m = row0 + wm * 32 + ml * 16 + g + rh * 8;
                int b = m >> 11, n = m & 2047;
                #pragma unroll
                for (int nl = 0; nl < 8; nl++) {
                    #pragma unroll
                    for (int e = 0; e < 2; e++) {
                        int c = col0 + wn * 64 + nl * 8 + 2 * t + e;
                        float v = acc[ml][nl][rh * 2 + e] + __ldg(bias + c);
                        int sel = c % 3;
                        int hd  = c / 3;
                        int h   = hd / 96;
                        int d   = hd - h * 96;
                        size_t o = ((size_t)(b * HH + h) * NN + n) * DD + d;
                        if (sel == 0)      g_Q[o] = v;
                        else if (sel == 1) g_K[o] = v;
                        else               g_V[o] = v;
                    }
                }
            }
        }
    }
}

// ---------------------------------------------------------------------------
// Kernel 2: flash attention on mma.sync tf32.
// BM=128 (8 warps x 16 rows, warp covers full key range -> warp-local softmax)
// BN=32 keys per tile. K,V in separate smem buffers [32][100] (pad 100 ->
// all fragment LDS conflict-free: bank = 4g+t (+8c) or 4t+g (+8c)).
// Q fragments register-resident (loaded once). P built from S C-frags by
// width-4 shuffles: C cols {2t,2t+1} -> A cols {t,t+4}.
// Softmax WITHOUT pre-scaling; SCALING applied after normalization.
// ---------------------------------------------------------------------------
__global__ __launch_bounds__(256) void attn_mma()
{
    __shared__ float sK[32 * 100];   // 12.8 KB
    __shared__ float sV[32 * 100];   // 12.8 KB

    const int tid  = threadIdx.x;
    const int lane = tid & 31;
    const int wid  = tid >> 5;       // 0..7, owns rows 16*wid .. 16*wid+15
    const int g    = lane >> 2;
    const int t    = lane & 3;
    const int q0   = blockIdx.x * 128;
    const int bh   = blockIdx.y;
    const int b    = bh >> 3;
    const int h    = bh & 7;

    const float* Qg = g_Q + (size_t)bh * NN * DD;
    const float* Kg = g_K + (size_t)bh * NN * DD;
    const float* Vg = g_V + (size_t)bh * NN * DD;

    const int r0 = 16 * wid + g;     // thread's row pair within tile
    const int r1 = r0 + 8;

    // ---- Q fragments, register-resident: 12 k-chunks x 4 regs ----
    uint32_t qf[12][4];
    {
        const float* Q0 = Qg + (size_t)(q0 + r0) * DD;
        const float* Q1 = Qg + (size_t)(q0 + r1) * DD;
        #pragma unroll
        for (int c = 0; c < 12; c++) {
            qf[c][0] = tf32r(Q0[8 * c + t]);
            qf[c][1] = tf32r(Q1[8 * c + t]);
            qf[c][2] = tf32r(Q0[8 * c + t + 4]);
            qf[c][3] = tf32r(Q1[8 * c + t + 4]);
        }
    }

    float m0 = -1e30f, m1 = -1e30f, l0 = 0.f, l1 = 0.f;
    float oacc[12][4];
    #pragma unroll
    for (int dc = 0; dc < 12; dc++)
        #pragma unroll
        for (int e = 0; e < 4; e++) oacc[dc][e] = 0.f;

    #pragma unroll 1
    for (int kt = 0; kt < 64; kt++) {          // 64 tiles of 32 keys
        const int j0 = kt * 32;
        __syncthreads();
        // load K,V tiles 32x96 each (3 float4 per thread per tensor)
        #pragma unroll
        for (int p = 0; p < 3; p++) {
            int i  = tid + p * 256;            // 768 float4s
            int r  = i / 24, c4 = i % 24;
            float4 kv = *(const float4*)(Kg + (size_t)(j0 + r) * DD + c4 * 4);
            float4 vv = *(const float4*)(Vg + (size_t)(j0 + r) * DD + c4 * 4);
            uint32_t* dk = (uint32_t*)&sK[r * 100 + c4 * 4];
            uint32_t* dv = (uint32_t*)&sV[r * 100 + c4 * 4];
            dk[0] = tf32r(kv.x); dk[1] = tf32r(kv.y);
            dk[2] = tf32r(kv.z); dk[3] = tf32r(kv.w);
            dv[0] = tf32r(vv.x); dv[1] = tf32r(vv.y);
            dv[2] = tf32r(vv.z); dv[3] = tf32r(vv.w);
        }
        __syncthreads();

        // ---- S = Q K^T : 4 n-chunks (8 keys each) x 12 k-chunks ----
        float sacc[4][4];
        #pragma unroll
        for (int nc = 0; nc < 4; nc++)
            #pragma unroll
            for (int e = 0; e < 4; e++) sacc[nc][e] = 0.f;

        const uint32_t* sKu = (const uint32_t*)sK;
        #pragma unroll
        for (int kc = 0; kc < 12; kc++) {
            #pragma unroll
            for (int nc = 0; nc < 4; nc++) {
                uint32_t bf[2];
                bf[0] = sKu[(nc * 8 + g) * 100 + kc * 8 + t];
                bf[1] = sKu[(nc * 8 + g) * 100 + kc * 8 + t + 4];
                mma_tf32(sacc[nc], qf[kc], bf);
            }
        }

        // ---- online softmax (rows r0, r1; quad = 4 lanes share a row) ----
        float lm0 = sacc[0][0], lm1 = sacc[0][2];
        #pragma unroll
        for (int nc = 0; nc < 4; nc++) {
            lm0 = fmaxf(lm0, fmaxf(sacc[nc][0], sacc[nc][1]));
            lm1 = fmaxf(lm1, fmaxf(sacc[nc][2], sacc[nc][3]));
        }
        lm0 = fmaxf(lm0, __shfl_xor_sync(0xffffffffu, lm0, 1));
        lm0 = fmaxf(lm0, __shfl_xor_sync(0xffffffffu, lm0, 2));
        lm1 = fmaxf(lm1, __shfl_xor_sync(0xffffffffu, lm1, 1));
        lm1 = fmaxf(lm1, __shfl_xor_sync(0xffffffffu, lm1, 2));

        const float mn0 = fmaxf(m0, lm0);
        const float mn1 = fmaxf(m1, lm1);
        const float sc0 = __expf(m0 - mn0);
        const float sc1 = __expf(m1 - mn1);
        m0 = mn0; m1 = mn1;

        float rs0 = 0.f, rs1 = 0.f;
        #pragma unroll
        for (int nc = 0; nc < 4; nc++) {
            sacc[nc][0] = __expf(sacc[nc][0] - mn0);
            sacc[nc][1] = __expf(sacc[nc][1] - mn0);
            sacc[nc][2] = __expf(sacc[nc][2] - mn1);
            sacc[nc][3] = __expf(sacc[nc][3] - mn1);
            rs0 += sacc[nc][0] + sacc[nc][1];
            rs1 += sacc[nc][2] + sacc[nc][3];
        }
        rs0 += __shfl_xor_sync(0xffffffffu, rs0, 1);
        rs0 += __shfl_xor_sync(0xffffffffu, rs0, 2);
        rs1 += __shfl_xor_sync(0xffffffffu, rs1, 1);
        rs1 += __shfl_xor_sync(0xffffffffu, rs1, 2);
        l0 = l0 * sc0 + rs0;
        l1 = l1 * sc1 + rs1;

        if (__any_sync(0xffffffffu, (sc0 != 1.f) || (sc1 != 1.f))) {
            #pragma unroll
            for (int dc = 0; dc < 12; dc++) {
                oacc[dc][0] *= sc0; oacc[dc][1] *= sc0;
                oacc[dc][2] *= sc1; oacc[dc][3] *= sc1;
            }
        }

        // ---- O += P @ V : 4 k-chunks (8 keys) x 12 d-chunks ----
        const uint32_t* sVu = (const uint32_t*)sV;
        const int s0 = t >> 1;          // quad-relative source lanes
        const int s1 = s0 + 2;
        #pragma unroll
        for (int kc = 0; kc < 4; kc++) {
            // P fragment: A cols {t, t+4} from C cols {2t, 2t+1} via shuffles
            uint32_t p0 = tf32r(sacc[kc][0]);
            uint32_t p1 = tf32r(sacc[kc][1]);
            uint32_t p2 = tf32r(sacc[kc][2]);
            uint32_t p3 = tf32r(sacc[kc][3]);
            uint32_t af[4];
            {
                uint32_t x0 = __shfl_sync(0xffffffffu, p0, s0, 4);
                uint32_t x1 = __shfl_sync(0xffffffffu, p1, s0, 4);
                uint32_t y0 = __shfl_sync(0xffffffffu, p0, s1, 4);
                uint32_t y1 = __shfl_sync(0xffffffffu, p1, s1, 4);
                af[0] = (t & 1) ? x1 : x0;
                af[2] = (t & 1) ? y1 : y0;
                uint32_t z0 = __shfl_sync(0xffffffffu, p2, s0, 4);
                uint32_t z1 = __shfl_sync(0xffffffffu, p3, s0, 4);
                uint32_t w0 = __shfl_sync(0xffffffffu, p2, s1, 4);
                uint32_t w1 = __shfl_sync(0xffffffffu, p3, s1, 4);
                af[1] = (t & 1) ? z1 : z0;
                af[3] = (t & 1) ? w1 : w0;
            }
            #pragma unroll
            for (int dc = 0; dc < 12; dc++) {
                uint32_t bf[2];
                bf[0] = sVu[(kc * 8 + t)     * 100 + dc * 8 + g];
                bf[1] = sVu[(kc * 8 + t + 4) * 100 + dc * 8 + g];
                mma_tf32(oacc[dc], af, bf);
            }
        }
    }

    // ---- epilogue: out = (O / l) * SCALING -> g_ctx[b][n][h*96 + d] ----
    const float inv0 = SCALING / l0;
    const float inv1 = SCALING / l1;
    float* dst0 = g_ctx + ((size_t)b * NN + (q0 + r0)) * EE + h * DD;
    float* dst1 = g_ctx + ((size_t)b * NN + (q0 + r1)) * EE + h * DD;
    #pragma unroll
    for (int dc = 0; dc < 12; dc++) {
        float2 o0, o1;
        o0.x = oacc[dc][0] * inv0; o0.y = oacc[dc][1] * inv0;
        o1.x = oacc[dc][2] * inv1; o1.y = oacc[dc][3] * inv1;
        *(float2*)(dst0 + dc * 8 + 2 * t) = o0;
        *(float2*)(dst1 + dc * 8 + 2 * t) = o1;
    }
}

// ---------------------------------------------------------------------------
extern "C" void kernel_launch(void* const* d_in, const int* in_sizes, int n_in,
                              void* d_out, int out_size)
{
    const float* x     = (const float*)d_in[0];
    const float* Wqkv  = (const float*)d_in[1];
    const float* bqkv  = (const float*)d_in[2];
    const float* Wproj = (const float*)d_in[3];
    const float* bproj = (const float*)d_in[4];
    float* out = (float*)d_out;

    dim3 g1(2304 / 128, 8192 / 128);      // 18 x 64
    gemm_mma<1, 2304><<<g1, 256>>>(x, Wqkv, bqkv, nullptr);

    dim3 g2(NN / 128, BB * HH);           // 16 x 32
    attn_mma<<<g2, 256>>>();

    dim3 g3(768 / 128, 8192 / 128);       // 6 x 64
    gemm_mma<0, 768><<<g3, 256>>>(nullptr, Wproj, bproj, out);
}

// round 7
// speedup vs baseline: 3.8047x; 1.3389x over previous
#include <cuda_runtime.h>
#include <cstdint>
#include <math.h>

// Problem constants
#define BB 4
#define NN 2048
#define EE 768
#define HH 8
#define DD 96
#define SCALING 0.1020620726159658f   // 96^-0.5

// Scratch (static device globals; no allocation). All tf32-pre-rounded.
__device__ float g_Q[BB * HH * NN * DD];    // [b][h][n][d]
__device__ float g_K[BB * HH * NN * DD];
__device__ float g_V[BB * HH * NN * DD];
__device__ float g_ctx[BB * NN * EE];       // [b][n][e]
__device__ float g_xr[BB * NN * EE];        // rounded x
__device__ float g_Wqkvr[EE * 3 * EE];      // rounded Wqkv
__device__ float g_Wprojr[EE * EE];         // rounded Wproj

// ---------------------------------------------------------------------------
// helpers
// ---------------------------------------------------------------------------
__device__ __forceinline__ uint32_t tf32r(float x) {
    uint32_t y;
    asm("cvt.rna.tf32.f32 %0, %1;" : "=r"(y) : "f"(x));
    return y;
}

__device__ __forceinline__ void mma_tf32(float* c, const uint32_t* a,
                                         const uint32_t* b) {
    asm volatile(
        "mma.sync.aligned.m16n8k8.row.col.f32.tf32.tf32.f32 "
        "{%0,%1,%2,%3}, {%4,%5,%6,%7}, {%8,%9}, {%0,%1,%2,%3};\n"
        : "+f"(c[0]), "+f"(c[1]), "+f"(c[2]), "+f"(c[3])
        : "r"(a[0]), "r"(a[1]), "r"(a[2]), "r"(a[3]), "r"(b[0]), "r"(b[1]));
}

__device__ __forceinline__ void cp16(void* smem_ptr, const void* gptr) {
    uint32_t sa = (uint32_t)__cvta_generic_to_shared(smem_ptr);
    asm volatile("cp.async.cg.shared.global [%0], [%1], 16;"
                 :: "r"(sa), "l"(gptr));
}
#define CP_COMMIT() asm volatile("cp.async.commit_group;" ::: "memory")
#define CP_WAIT0()  asm volatile("cp.async.wait_group 0;" ::: "memory")

// ---------------------------------------------------------------------------
// Kernel 0: tf32-round inputs into device scratch (dst resolved device-side!)
// ---------------------------------------------------------------------------
__global__ void round_into(const float4* __restrict__ src, int n4, int sel)
{
    float4* dst = (sel == 0) ? (float4*)g_xr
               : (sel == 1) ? (float4*)g_Wqkvr
                            : (float4*)g_Wprojr;
    int i = blockIdx.x * blockDim.x + threadIdx.x;
    if (i < n4) {
        float4 v = src[i];
        v.x = __uint_as_float(tf32r(v.x));
        v.y = __uint_as_float(tf32r(v.y));
        v.z = __uint_as_float(tf32r(v.z));
        v.w = __uint_as_float(tf32r(v.w));
        dst[i] = v;
    }
}

// ---------------------------------------------------------------------------
// Tensor-core tf32 GEMM, cp.async double-buffered.
// C[8192,LDW] = A[8192,768] @ W[768,LDW] + bias. Tile 128x128x32, 8 warps.
// All operands pre-rounded -> raw cp.async, no cvt, no staging regs.
// MODE 1 (qkv): A=g_xr, W=g_Wqkvr, scatter rounded into g_Q/g_K/g_V.
// MODE 0 (proj): A=g_ctx, W=g_Wprojr, write fp32 out.
// ---------------------------------------------------------------------------
#define APAD 36
#define BPAD 136
#define ASZ (128 * APAD)       // 4608 floats
#define BSZ (32 * BPAD)        // 4352 floats
#define GSTG (ASZ + BSZ)       // 8960 floats = 35840 B
#define GSMEM (2 * GSTG * 4)   // 71680 B

template<int MODE, int LDW>
__global__ __launch_bounds__(256, 2) void gemm_tc(
    const float* __restrict__ bias,
    float* __restrict__ out)
{
    extern __shared__ float sm[];
    const float* A = (MODE == 0) ? (const float*)g_ctx : (const float*)g_xr;
    const float* W = (MODE == 0) ? (const float*)g_Wprojr : (const float*)g_Wqkvr;

    const int tid  = threadIdx.x;
    const int lane = tid & 31;
    const int wid  = tid >> 5;
    const int wm   = wid & 3;
    const int wn   = wid >> 2;
    const int row0 = blockIdx.y * 128;
    const int col0 = blockIdx.x * 128;
    const int g    = lane >> 2;
    const int t    = lane & 3;

    float acc[2][8][4];
    #pragma unroll
    for (int ml = 0; ml < 2; ml++)
        #pragma unroll
        for (int nl = 0; nl < 8; nl++)
            #pragma unroll
            for (int e = 0; e < 4; e++) acc[ml][nl][e] = 0.f;

    auto issue = [&](int kt, int s) {
        float* sA = sm + s * GSTG;
        float* sB = sA + ASZ;
        #pragma unroll
        for (int p = 0; p < 4; p++) {
            int i = tid + p * 256;
            int m = i >> 3, k4 = i & 7;
            cp16(sA + m * APAD + k4 * 4,
                 A + (size_t)(row0 + m) * 768 + kt * 32 + k4 * 4);
        }
        #pragma unroll
        for (int p = 0; p < 4; p++) {
            int i = tid + p * 256;
            int k = i >> 5, n4 = i & 31;
            cp16(sB + k * BPAD + n4 * 4,
                 W + (size_t)(kt * 32 + k) * LDW + col0 + n4 * 4);
        }
        CP_COMMIT();
    };

    issue(0, 0);

    #pragma unroll 1
    for (int kt = 0; kt < 24; kt++) {
        const int s = kt & 1;
        CP_WAIT0();
        __syncthreads();
        if (kt < 23) issue(kt + 1, s ^ 1);

        const uint32_t* sA = (const uint32_t*)(sm + s * GSTG);
        const uint32_t* sB = sA + ASZ;

        #pragma unroll
        for (int ks = 0; ks < 4; ks++) {
            const int k0 = ks * 8;
            uint32_t af[2][4];
            #pragma unroll
            for (int ml = 0; ml < 2; ml++) {
                const int m_off = wm * 32 + ml * 16;
                af[ml][0] = sA[(m_off + g)     * APAD + k0 + t];
                af[ml][1] = sA[(m_off + g + 8) * APAD + k0 + t];
                af[ml][2] = sA[(m_off + g)     * APAD + k0 + t + 4];
                af[ml][3] = sA[(m_off + g + 8) * APAD + k0 + t + 4];
            }
            #pragma unroll
            for (int nl = 0; nl < 8; nl++) {
                const int n_off = wn * 64 + nl * 8;
                uint32_t bf[2];
                bf[0] = sB[(k0 + t)     * BPAD + n_off + g];
                bf[1] = sB[(k0 + t + 4) * BPAD + n_off + g];
                mma_tf32(acc[0][nl], af[0], bf);
                mma_tf32(acc[1][nl], af[1], bf);
            }
        }
    }

    // ---- epilogue ----
    if (MODE == 0) {
        #pragma unroll
        for (int ml = 0; ml < 2; ml++) {
            #pragma unroll
            for (int rh = 0; rh < 2; rh++) {
                int m = row0 + wm * 32 + ml * 16 + g + rh * 8;
                float* op = out + (size_t)m * LDW;
                #pragma unroll
                for (int nl = 0; nl < 8; nl++) {
                    int c = col0 + wn * 64 + nl * 8 + 2 * t;
                    float2 bv = *(const float2*)(bias + c);
                    float2 o;
                    o.x = acc[ml][nl][rh * 2 + 0] + bv.x;
                    o.y = acc[ml][nl][rh * 2 + 1] + bv.y;
                    *(float2*)(op + c) = o;
                }
            }
        }
    } else {
        #pragma unroll
        for (int ml = 0; ml < 2; ml++) {
            #pragma unroll
            for (int rh = 0; rh < 2; rh++) {
                int m = row0 + wm * 32 + ml * 16 + g + rh * 8;
                int b = m >> 11, n = m & 2047;
                #pragma unroll
                for (int nl = 0; nl < 8; nl++) {
                    #pragma unroll
                    for (int e = 0; e < 2; e++) {
                        int c = col0 + wn * 64 + nl * 8 + 2 * t + e;
                        float v = acc[ml][nl][rh * 2 + e] + __ldg(bias + c);
                        int sel = c % 3;
                        int hd  = c / 3;
                        int h   = hd / 96;
                        int d   = hd - h * 96;
                        size_t o = ((size_t)(b * HH + h) * NN + n) * DD + d;
                        float vr = __uint_as_float(tf32r(v));
                        if (sel == 0)      g_Q[o] = vr;
                        else if (sel == 1) g_K[o] = vr;
                        else               g_V[o] = vr;
                    }
                }
            }
        }
    }
}

// ---------------------------------------------------------------------------
// Kernel 2: flash attention on mma.sync tf32, cp.async double-buffered K/V.
// BM=128 (8 warps x 16 rows -> warp-local softmax), BN=32 per tile.
// K,V pre-rounded -> raw cp.async. Pads of 100 keep frag LDS conflict-free.
// Softmax without pre-scaling; SCALING applied after normalization.
// ---------------------------------------------------------------------------
#define KVSZ 3200                 // 32*100 floats
#define ASTG (2 * KVSZ)           // K+V per stage
#define ASMEM (2 * ASTG * 4)      // 51200 B

__global__ __launch_bounds__(256) void attn_mma()
{
    extern __shared__ float sm[];

    const int tid  = threadIdx.x;
    const int lane = tid & 31;
    const int wid  = tid >> 5;
    const int g    = lane >> 2;
    const int t    = lane & 3;
    const int q0   = blockIdx.x * 128;
    const int bh   = blockIdx.y;
    const int b    = bh >> 3;
    const int h    = bh & 7;

    const float* Qg = g_Q + (size_t)bh * NN * DD;
    const float* Kg = g_K + (size_t)bh * NN * DD;
    const float* Vg = g_V + (size_t)bh * NN * DD;

    const int r0 = 16 * wid + g;
    const int r1 = r0 + 8;

    auto issueKV = [&](int kt, int s) {
        const int j0 = kt * 32;
        float* bK = sm + s * ASTG;
        float* bV = bK + KVSZ;
        #pragma unroll
        for (int p = 0; p < 3; p++) {
            int i  = tid + p * 256;
            int r  = i / 24, c4 = i % 24;
            cp16(bK + r * 100 + c4 * 4, Kg + (size_t)(j0 + r) * DD + c4 * 4);
            cp16(bV + r * 100 + c4 * 4, Vg + (size_t)(j0 + r) * DD + c4 * 4);
        }
        CP_COMMIT();
    };

    issueKV(0, 0);

    // Q fragments, register-resident (pre-rounded -> raw bits)
    uint32_t qf[12][4];
    {
        const uint32_t* Q0 = (const uint32_t*)(Qg + (size_t)(q0 + r0) * DD);
        const uint32_t* Q1 = (const uint32_t*)(Qg + (size_t)(q0 + r1) * DD);
        #pragma unroll
        for (int c = 0; c < 12; c++) {
            qf[c][0] = Q0[8 * c + t];
            qf[c][1] = Q1[8 * c + t];
            qf[c][2] = Q0[8 * c + t + 4];
            qf[c][3] = Q1[8 * c + t + 4];
        }
    }

    float m0 = -1e30f, m1 = -1e30f, l0 = 0.f, l1 = 0.f;
    float oacc[12][4];
    #pragma unroll
    for (int dc = 0; dc < 12; dc++)
        #pragma unroll
        for (int e = 0; e < 4; e++) oacc[dc][e] = 0.f;

    #pragma unroll 1
    for (int kt = 0; kt < 64; kt++) {
        const int s = kt & 1;
        CP_WAIT0();
        __syncthreads();
        if (kt < 63) issueKV(kt + 1, s ^ 1);

        const uint32_t* sKu = (const uint32_t*)(sm + s * ASTG);
        const uint32_t* sVu = sKu + KVSZ;

        // ---- S = Q K^T ----
        float sacc[4][4];
        #pragma unroll
        for (int nc = 0; nc < 4; nc++)
            #pragma unroll
            for (int e = 0; e < 4; e++) sacc[nc][e] = 0.f;

        #pragma unroll
        for (int kc = 0; kc < 12; kc++) {
            #pragma unroll
            for (int nc = 0; nc < 4; nc++) {
                uint32_t bf[2];
                bf[0] = sKu[(nc * 8 + g) * 100 + kc * 8 + t];
                bf[1] = sKu[(nc * 8 + g) * 100 + kc * 8 + t + 4];
                mma_tf32(sacc[nc], qf[kc], bf);
            }
        }

        // ---- online softmax ----
        float lm0 = sacc[0][0], lm1 = sacc[0][2];
        #pragma unroll
        for (int nc = 0; nc < 4; nc++) {
            lm0 = fmaxf(lm0, fmaxf(sacc[nc][0], sacc[nc][1]));
            lm1 = fmaxf(lm1, fmaxf(sacc[nc][2], sacc[nc][3]));
        }
        lm0 = fmaxf(lm0, __shfl_xor_sync(0xffffffffu, lm0, 1));
        lm0 = fmaxf(lm0, __shfl_xor_sync(0xffffffffu, lm0, 2));
        lm1 = fmaxf(lm1, __shfl_xor_sync(0xffffffffu, lm1, 1));
        lm1 = fmaxf(lm1, __shfl_xor_sync(0xffffffffu, lm1, 2));

        const float mn0 = fmaxf(m0, lm0);
        const float mn1 = fmaxf(m1, lm1);
        const float sc0 = __expf(m0 - mn0);
        const float sc1 = __expf(m1 - mn1);
        m0 = mn0; m1 = mn1;

        float rs0 = 0.f, rs1 = 0.f;
        #pragma unroll
        for (int nc = 0; nc < 4; nc++) {
            sacc[nc][0] = __expf(sacc[nc][0] - mn0);
            sacc[nc][1] = __expf(sacc[nc][1] - mn0);
            sacc[nc][2] = __expf(sacc[nc][2] - mn1);
            sacc[nc][3] = __expf(sacc[nc][3] - mn1);
            rs0 += sacc[nc][0] + sacc[nc][1];
            rs1 += sacc[nc][2] + sacc[nc][3];
        }
        rs0 += __shfl_xor_sync(0xffffffffu, rs0, 1);
        rs0 += __shfl_xor_sync(0xffffffffu, rs0, 2);
        rs1 += __shfl_xor_sync(0xffffffffu, rs1, 1);
        rs1 += __shfl_xor_sync(0xffffffffu, rs1, 2);
        l0 = l0 * sc0 + rs0;
        l1 = l1 * sc1 + rs1;

        if (__any_sync(0xffffffffu, (sc0 != 1.f) || (sc1 != 1.f))) {
            #pragma unroll
            for (int dc = 0; dc < 12; dc++) {
                oacc[dc][0] *= sc0; oacc[dc][1] *= sc0;
                oacc[dc][2] *= sc1; oacc[dc][3] *= sc1;
            }
        }

        // ---- O += P @ V ----
        const int s0 = t >> 1;
        const int s1 = s0 + 2;
        #pragma unroll
        for (int kc = 0; kc < 4; kc++) {
            uint32_t p0 = tf32r(sacc[kc][0]);
            uint32_t p1 = tf32r(sacc[kc][1]);
            uint32_t p2 = tf32r(sacc[kc][2]);
            uint32_t p3 = tf32r(sacc[kc][3]);
            uint32_t af[4];
            {
                uint32_t x0 = __shfl_sync(0xffffffffu, p0, s0, 4);
                uint32_t x1 = __shfl_sync(0xffffffffu, p1, s0, 4);
                uint32_t y0 = __shfl_sync(0xffffffffu, p0, s1, 4);
                uint32_t y1 = __shfl_sync(0xffffffffu, p1, s1, 4);
                af[0] = (t & 1) ? x1 : x0;
                af[2] = (t & 1) ? y1 : y0;
                uint32_t z0 = __shfl_sync(0xffffffffu, p2, s0, 4);
                uint32_t z1 = __shfl_sync(0xffffffffu, p3, s0, 4);
                uint32_t w0 = __shfl_sync(0xffffffffu, p2, s1, 4);
                uint32_t w1 = __shfl_sync(0xffffffffu, p3, s1, 4);
                af[1] = (t & 1) ? z1 : z0;
                af[3] = (t & 1) ? w1 : w0;
            }
            #pragma unroll
            for (int dc = 0; dc < 12; dc++) {
                uint32_t bf[2];
                bf[0] = sVu[(kc * 8 + t)     * 100 + dc * 8 + g];
                bf[1] = sVu[(kc * 8 + t + 4) * 100 + dc * 8 + g];
                mma_tf32(oacc[dc], af, bf);
            }
        }
    }

    // ---- epilogue: ctx = tf32r((O / l) * SCALING) ----
    const float inv0 = SCALING / l0;
    const float inv1 = SCALING / l1;
    float* dst0 = g_ctx + ((size_t)b * NN + (q0 + r0)) * EE + h * DD;
    float* dst1 = g_ctx + ((size_t)b * NN + (q0 + r1)) * EE + h * DD;
    #pragma unroll
    for (int dc = 0; dc < 12; dc++) {
        float2 o0, o1;
        o0.x = __uint_as_float(tf32r(oacc[dc][0] * inv0));
        o0.y = __uint_as_float(tf32r(oacc[dc][1] * inv0));
        o1.x = __uint_as_float(tf32r(oacc[dc][2] * inv1));
        o1.y = __uint_as_float(tf32r(oacc[dc][3] * inv1));
        *(float2*)(dst0 + dc * 8 + 2 * t) = o0;
        *(float2*)(dst1 + dc * 8 + 2 * t) = o1;
    }
}

// ---------------------------------------------------------------------------
extern "C" void kernel_launch(void* const* d_in, const int* in_sizes, int n_in,
                              void* d_out, int out_size)
{
    const float* x     = (const float*)d_in[0];
    const float* Wqkv  = (const float*)d_in[1];
    const float* bqkv  = (const float*)d_in[2];
    const float* Wproj = (const float*)d_in[3];
    const float* bproj = (const float*)d_in[4];
    float* out = (float*)d_out;

    cudaFuncSetAttribute(gemm_tc<1, 2304>,
                         cudaFuncAttributeMaxDynamicSharedMemorySize, GSMEM);
    cudaFuncSetAttribute(gemm_tc<0, 768>,
                         cudaFuncAttributeMaxDynamicSharedMemorySize, GSMEM);
    cudaFuncSetAttribute(attn_mma,
                         cudaFuncAttributeMaxDynamicSharedMemorySize, ASMEM);

    // pre-round inputs (tf32 RNA)
    round_into<<<(1572864 + 255) / 256, 256>>>((const float4*)x,     1572864, 0);
    round_into<<<(442368  + 255) / 256, 256>>>((const float4*)Wqkv,  442368,  1);
    round_into<<<(147456  + 255) / 256, 256>>>((const float4*)Wproj, 147456,  2);

    dim3 g1(2304 / 128, 8192 / 128);      // 18 x 64
    gemm_tc<1, 2304><<<g1, 256, GSMEM>>>(bqkv, nullptr);

    dim3 g2(NN / 128, BB * HH);           // 16 x 32
    attn_mma<<<g2, 256, ASMEM>>>();

    dim3 g3(768 / 128, 8192 / 128);       // 6 x 64
    gemm_tc<0, 768><<<g3, 256, GSMEM>>>(bproj, out);
}

// round 8
// speedup vs baseline: 4.0899x; 1.0750x over previous
#include <cuda_runtime.h>
#include <cstdint>
#include <math.h>

// Problem constants
#define BB 4
#define NN 2048
#define EE 768
#define HH 8
#define DD 96
#define SCALING 0.1020620726159658f   // 96^-0.5

// Scratch (static device globals; no allocation). All tf32-pre-rounded.
// g_Q, g_K, g_xr, g_Wqkvt use the within-8 k/d permutation k'=(k&3)*2+(k>>2).
__device__ float g_Q[BB * HH * NN * DD];    // [b][h][n][d']  (permuted d)
__device__ float g_K[BB * HH * NN * DD];    // [b][h][n][d']  (permuted d)
__device__ float g_V[BB * HH * NN * DD];    // [b][h][n][d]   (plain d)
__device__ float g_ctx[BB * NN * EE];       // [b][n][e]      (plain e)
__device__ float g_xr[BB * NN * EE];        // rounded x, permuted k
__device__ float g_Wqkvt[EE * 3 * EE];      // rounded Wqkv^T [2304][768], permuted k
__device__ float g_Wprojt[EE * EE];         // rounded Wproj^T [768][768], plain k

// ---------------------------------------------------------------------------
// helpers
// ---------------------------------------------------------------------------
__device__ __forceinline__ uint32_t tf32r(float x) {
    uint32_t y;
    asm("cvt.rna.tf32.f32 %0, %1;" : "=r"(y) : "f"(x));
    return y;
}

__device__ __forceinline__ int perm8(int k) {           // within-8 permutation
    return (k & ~7) | (((k & 3) << 1) | ((k >> 2) & 1));
}

__device__ __forceinline__ void mma_tf32(float* c, const uint32_t* a,
                                         const uint32_t* b) {
    asm volatile(
        "mma.sync.aligned.m16n8k8.row.col.f32.tf32.tf32.f32 "
        "{%0,%1,%2,%3}, {%4,%5,%6,%7}, {%8,%9}, {%0,%1,%2,%3};\n"
        : "+f"(c[0]), "+f"(c[1]), "+f"(c[2]), "+f"(c[3])
        : "r"(a[0]), "r"(a[1]), "r"(a[2]), "r"(a[3]), "r"(b[0]), "r"(b[1]));
}

__device__ __forceinline__ void cp16(void* smem_ptr, const void* gptr) {
    uint32_t sa = (uint32_t)__cvta_generic_to_shared(smem_ptr);
    asm volatile("cp.async.cg.shared.global [%0], [%1], 16;"
                 :: "r"(sa), "l"(gptr));
}
#define CP_COMMIT() asm volatile("cp.async.commit_group;" ::: "memory")
#define CP_WAIT0()  asm volatile("cp.async.wait_group 0;" ::: "memory")

// ---------------------------------------------------------------------------
// Pre-pass 1: round + permute x -> g_xr. Read float4, write 4 scalars.
// ---------------------------------------------------------------------------
__global__ void round_perm_x(const float4* __restrict__ src, int n4)
{
    int i = blockIdx.x * blockDim.x + threadIdx.x;
    if (i >= n4) return;
    float4 v = src[i];
    int base = i * 4;                  // element index; row stride 768
    int row = base / 768, k = base % 768;
    float* dst = g_xr + (size_t)row * 768;
    dst[perm8(k + 0)] = __uint_as_float(tf32r(v.x));
    dst[perm8(k + 1)] = __uint_as_float(tf32r(v.y));
    dst[perm8(k + 2)] = __uint_as_float(tf32r(v.z));
    dst[perm8(k + 3)] = __uint_as_float(tf32r(v.w));
}

// ---------------------------------------------------------------------------
// Pre-pass 2: round + transpose W[k][N] -> Wt[N][768] (+ optional k-perm)
// block (32,8), 32x32 tiles.
// ---------------------------------------------------------------------------
template<int PERM>
__global__ void transpose_round(const float* __restrict__ src, int N, int sel)
{
    __shared__ float tile[32][33];
    float* dst = sel ? (float*)g_Wqkvt : (float*)g_Wprojt;

    const int n0 = blockIdx.x * 32;
    const int k0 = blockIdx.y * 32;
    const int tx = threadIdx.x, ty = threadIdx.y;

    #pragma unroll
    for (int j = 0; j < 4; j++) {
        float v = src[(size_t)(k0 + ty + 8 * j) * N + n0 + tx];
        tile[ty + 8 * j][tx] = __uint_as_float(tf32r(v));
    }
    __syncthreads();
    const int kp = PERM ? perm8(tx) : tx;
    #pragma unroll
    for (int j = 0; j < 4; j++) {
        dst[(size_t)(n0 + ty + 8 * j) * 768 + k0 + kp] = tile[tx][ty + 8 * j];
    }
}

// ---------------------------------------------------------------------------
// Tensor-core tf32 GEMM, cp.async double-buffered, transposed B.
// C[8192, NCOLS] = A[8192,768] @ Wt[NCOLS,768]^T + bias. Tile 128x128x32.
// MODE 1 (qkv): A=g_xr (perm k), B=g_Wqkvt (perm k) -> uint2 frag loads.
//               Scatter rounded into g_Q/g_K (perm d) and g_V (plain d).
// MODE 0 (proj): A=g_ctx, B=g_Wprojt (both plain k) -> scalar frag loads.
// smem per stage: A[128][40] + B[128][40]  (pad 40 -> conflict-free frags)
// ---------------------------------------------------------------------------
#define TPAD 40
#define TSZ  (128 * TPAD)        // 5120 floats per operand
#define GSTG (2 * TSZ)           // 10240 floats per stage
#define GSMEM (2 * GSTG * 4)     // 81920 B

template<int MODE>
__global__ __launch_bounds__(256, 2) void gemm_tc(
    const float* __restrict__ bias,
    float* __restrict__ out)
{
    extern __shared__ float sm[];
    const float* A = (MODE == 0) ? (const float*)g_ctx : (const float*)g_xr;
    const float* Wt = (MODE == 0) ? (const float*)g_Wprojt : (const float*)g_Wqkvt;

    const int tid  = threadIdx.x;
    const int lane = tid & 31;
    const int wid  = tid >> 5;
    const int wm   = wid & 3;
    const int wn   = wid >> 2;
    const int row0 = blockIdx.y * 128;
    const int col0 = blockIdx.x * 128;
    const int g    = lane >> 2;
    const int t    = lane & 3;

    float acc[2][8][4];
    #pragma unroll
    for (int ml = 0; ml < 2; ml++)
        #pragma unroll
        for (int nl = 0; nl < 8; nl++)
            #pragma unroll
            for (int e = 0; e < 4; e++) acc[ml][nl][e] = 0.f;

    auto issue = [&](int kt, int s) {
        float* sA = sm + s * GSTG;
        float* sB = sA + TSZ;
        #pragma unroll
        for (int p = 0; p < 4; p++) {
            int i = tid + p * 256;
            int m = i >> 3, k4 = i & 7;        // 128 rows x 8 float4
            cp16(sA + m * TPAD + k4 * 4,
                 A + (size_t)(row0 + m) * 768 + kt * 32 + k4 * 4);
        }
        #pragma unroll
        for (int p = 0; p < 4; p++) {
            int i = tid + p * 256;
            int n = i >> 3, k4 = i & 7;        // 128 rows x 8 float4
            cp16(sB + n * TPAD + k4 * 4,
                 Wt + (size_t)(col0 + n) * 768 + kt * 32 + k4 * 4);
        }
        CP_COMMIT();
    };

    issue(0, 0);

    #pragma unroll 1
    for (int kt = 0; kt < 24; kt++) {
        const int s = kt & 1;
        CP_WAIT0();
        __syncthreads();
        if (kt < 23) issue(kt + 1, s ^ 1);

        const uint32_t* sA = (const uint32_t*)(sm + s * GSTG);
        const uint32_t* sB = sA + TSZ;

        #pragma unroll
        for (int ks = 0; ks < 4; ks++) {
            const int k0 = ks * 8;
            uint32_t af[2][4];
            #pragma unroll
            for (int ml = 0; ml < 2; ml++) {
                const int m_off = wm * 32 + ml * 16;
                if (MODE == 1) {
                    uint2 lo = *(const uint2*)&sA[(m_off + g)     * TPAD + k0 + 2 * t];
                    uint2 hi = *(const uint2*)&sA[(m_off + g + 8) * TPAD + k0 + 2 * t];
                    af[ml][0] = lo.x; af[ml][2] = lo.y;
                    af[ml][1] = hi.x; af[ml][3] = hi.y;
                } else {
                    af[ml][0] = sA[(m_off + g)     * TPAD + k0 + t];
                    af[ml][1] = sA[(m_off + g + 8) * TPAD + k0 + t];
                    af[ml][2] = sA[(m_off + g)     * TPAD + k0 + t + 4];
                    af[ml][3] = sA[(m_off + g + 8) * TPAD + k0 + t + 4];
                }
            }
            #pragma unroll
            for (int nl = 0; nl < 8; nl++) {
                const int n_off = wn * 64 + nl * 8;
                uint32_t bf[2];
                if (MODE == 1) {
                    uint2 v = *(const uint2*)&sB[(n_off + g) * TPAD + k0 + 2 * t];
                    bf[0] = v.x; bf[1] = v.y;
                } else {
                    bf[0] = sB[(n_off + g) * TPAD + k0 + t];
                    bf[1] = sB[(n_off + g) * TPAD + k0 + t + 4];
                }
                mma_tf32(acc[0][nl], af[0], bf);
                mma_tf32(acc[1][nl], af[1], bf);
            }
        }
    }

    // ---- epilogue ----
    if (MODE == 0) {
        #pragma unroll
        for (int ml = 0; ml < 2; ml++) {
            #pragma unroll
            for (int rh = 0; rh < 2; rh++) {
                int m = row0 + wm * 32 + ml * 16 + g + rh * 8;
                float* op = out + (size_t)m * 768;
                #pragma unroll
                for (int nl = 0; nl < 8; nl++) {
                    int c = col0 + wn * 64 + nl * 8 + 2 * t;
                    float2 bv = *(const float2*)(bias + c);
                    float2 o;
                    o.x = acc[ml][nl][rh * 2 + 0] + bv.x;
                    o.y = acc[ml][nl][rh * 2 + 1] + bv.y;
                    *(float2*)(op + c) = o;
                }
            }
        }
    } else {
        #pragma unroll
        for (int ml = 0; ml < 2; ml++) {
            #pragma unroll
            for (int rh = 0; rh < 2; rh++) {
                int m = row0 + wm * 32 + ml * 16 + g + rh * 8;
                int b = m >> 11, n = m & 2047;
                #pragma unroll
                for (int nl = 0; nl < 8; nl++) {
                    #pragma unroll
                    for (int e = 0; e < 2; e++) {
                        int c = col0 + wn * 64 + nl * 8 + 2 * t + e;
                        float v = acc[ml][nl][rh * 2 + e] + __ldg(bias + c);
                        int sel = c % 3;
                        int hd  = c / 3;
                        int h   = hd / 96;
                        int d   = hd - h * 96;
                        float vr = __uint_as_float(tf32r(v));
                        size_t rowo = ((size_t)(b * HH + h) * NN + n) * DD;
                        if (sel == 0)      g_Q[rowo + perm8(d)] = vr;
                        else if (sel == 1) g_K[rowo + perm8(d)] = vr;
                        else               g_V[rowo + d]        = vr;
                    }
                }
            }
        }
    }
}

// ---------------------------------------------------------------------------
// Flash attention on mma.sync tf32, cp.async double-buffered K/V.
// BM=128 (8 warps x 16 rows -> warp-local softmax), BN=32 per tile.
// g_Q/g_K permuted d -> uint2 fragment loads. Pad 104 keeps LDS.64 and
// scalar V frags conflict-free. SCALING applied after normalization.
// ---------------------------------------------------------------------------
#define KVPAD 104
#define KVSZ (32 * KVPAD)         // 3328 floats
#define ASTG (2 * KVSZ)           // K+V per stage
#define ASMEM (2 * ASTG * 4)      // 53248 B

__global__ __launch_bounds__(256) void attn_mma()
{
    extern __shared__ float sm[];

    const int tid  = threadIdx.x;
    const int lane = tid & 31;
    const int wid  = tid >> 5;
    const int g    = lane >> 2;
    const int t    = lane & 3;
    const int q0   = blockIdx.x * 128;
    const int bh   = blockIdx.y;
    const int b    = bh >> 3;
    const int h    = bh & 7;

    const float* Qg = g_Q + (size_t)bh * NN * DD;
    const float* Kg = g_K + (size_t)bh * NN * DD;
    const float* Vg = g_V + (size_t)bh * NN * DD;

    const int r0 = 16 * wid + g;
    const int r1 = r0 + 8;

    auto issueKV = [&](int kt, int s) {
        const int j0 = kt * 32;
        float* bK = sm + s * ASTG;
        float* bV = bK + KVSZ;
        #pragma unroll
        for (int p = 0; p < 3; p++) {
            int i  = tid + p * 256;
            int r  = i / 24, c4 = i % 24;
            cp16(bK + r * KVPAD + c4 * 4, Kg + (size_t)(j0 + r) * DD + c4 * 4);
            cp16(bV + r * KVPAD + c4 * 4, Vg + (size_t)(j0 + r) * DD + c4 * 4);
        }
        CP_COMMIT();
    };

    issueKV(0, 0);

    // Q fragments register-resident: permuted storage -> uint2 per pair
    uint32_t qf[12][4];
    {
        const uint32_t* Q0 = (const uint32_t*)(Qg + (size_t)(q0 + r0) * DD);
        const uint32_t* Q1 = (const uint32_t*)(Qg + (size_t)(q0 + r1) * DD);
        #pragma unroll
        for (int c = 0; c < 12; c++) {
            uint2 v0 = *(const uint2*)&Q0[8 * c + 2 * t];
            uint2 v1 = *(const uint2*)&Q1[8 * c + 2 * t];
            qf[c][0] = v0.x; qf[c][2] = v0.y;
            qf[c][1] = v1.x; qf[c][3] = v1.y;
        }
    }

    float m0 = -1e30f, m1 = -1e30f, l0 = 0.f, l1 = 0.f;
    float oacc[12][4];
    #pragma unroll
    for (int dc = 0; dc < 12; dc++)
        #pragma unroll
        for (int e = 0; e < 4; e++) oacc[dc][e] = 0.f;

    #pragma unroll 1
    for (int kt = 0; kt < 64; kt++) {
        const int s = kt & 1;
        CP_WAIT0();
        __syncthreads();
        if (kt < 63) issueKV(kt + 1, s ^ 1);

        const uint32_t* sKu = (const uint32_t*)(sm + s * ASTG);
        const uint32_t* sVu = sKu + KVSZ;

        // ---- S = Q K^T (K permuted -> uint2 frag loads) ----
        float sacc[4][4];
        #pragma unroll
        for (int nc = 0; nc < 4; nc++)
            #pragma unroll
            for (int e = 0; e < 4; e++) sacc[nc][e] = 0.f;

        #pragma unroll
        for (int kc = 0; kc < 12; kc++) {
            #pragma unroll
            for (int nc = 0; nc < 4; nc++) {
                uint2 v = *(const uint2*)&sKu[(nc * 8 + g) * KVPAD + kc * 8 + 2 * t];
                uint32_t bf[2] = { v.x, v.y };
                mma_tf32(sacc[nc], qf[kc], bf);
            }
        }

        // ---- online softmax ----
        float lm0 = sacc[0][0], lm1 = sacc[0][2];
        #pragma unroll
        for (int nc = 0; nc < 4; nc++) {
            lm0 = fmaxf(lm0, fmaxf(sacc[nc][0], sacc[nc][1]));
            lm1 = fmaxf(lm1, fmaxf(sacc[nc][2], sacc[nc][3]));
        }
        lm0 = fmaxf(lm0, __shfl_xor_sync(0xffffffffu, lm0, 1));
        lm0 = fmaxf(lm0, __shfl_xor_sync(0xffffffffu, lm0, 2));
        lm1 = fmaxf(lm1, __shfl_xor_sync(0xffffffffu, lm1, 1));
        lm1 = fmaxf(lm1, __shfl_xor_sync(0xffffffffu, lm1, 2));

        const float mn0 = fmaxf(m0, lm0);
        const float mn1 = fmaxf(m1, lm1);
        const float sc0 = __expf(m0 - mn0);
        const float sc1 = __expf(m1 - mn1);
        m0 = mn0; m1 = mn1;

        float rs0 = 0.f, rs1 = 0.f;
        #pragma unroll
        for (int nc = 0; nc < 4; nc++) {
            sacc[nc][0] = __expf(sacc[nc][0] - mn0);
            sacc[nc][1] = __expf(sacc[nc][1] - mn0);
            sacc[nc][2] = __expf(sacc[nc][2] - mn1);
            sacc[nc][3] = __expf(sacc[nc][3] - mn1);
            rs0 += sacc[nc][0] + sacc[nc][1];
            rs1 += sacc[nc][2] + sacc[nc][3];
        }
        rs0 += __shfl_xor_sync(0xffffffffu, rs0, 1);
        rs0 += __shfl_xor_sync(0xffffffffu, rs0, 2);
        rs1 += __shfl_xor_sync(0xffffffffu, rs1, 1);
        rs1 += __shfl_xor_sync(0xffffffffu, rs1, 2);
        l0 = l0 * sc0 + rs0;
        l1 = l1 * sc1 + rs1;

        if (__any_sync(0xffffffffu, (sc0 != 1.f) || (sc1 != 1.f))) {
            #pragma unroll
            for (int dc = 0; dc < 12; dc++) {
                oacc[dc][0] *= sc0; oacc[dc][1] *= sc0;
                oacc[dc][2] *= sc1; oacc[dc][3] *= sc1;
            }
        }

        // ---- O += P @ V ----
        const int s0 = t >> 1;
        const int s1 = s0 + 2;
        #pragma unroll
        for (int kc = 0; kc < 4; kc++) {
            uint32_t p0 = tf32r(sacc[kc][0]);
            uint32_t p1 = tf32r(sacc[kc][1]);
            uint32_t p2 = tf32r(sacc[kc][2]);
            uint32_t p3 = tf32r(sacc[kc][3]);
            uint32_t af[4];
            {
                uint32_t x0 = __shfl_sync(0xffffffffu, p0, s0, 4);
                uint32_t x1 = __shfl_sync(0xffffffffu, p1, s0, 4);
                uint32_t y0 = __shfl_sync(0xffffffffu, p0, s1, 4);
                uint32_t y1 = __shfl_sync(0xffffffffu, p1, s1, 4);
                af[0] = (t & 1) ? x1 : x0;
                af[2] = (t & 1) ? y1 : y0;
                uint32_t z0 = __shfl_sync(0xffffffffu, p2, s0, 4);
                uint32_t z1 = __shfl_sync(0xffffffffu, p3, s0, 4);
                uint32_t w0 = __shfl_sync(0xffffffffu, p2, s1, 4);
                uint32_t w1 = __shfl_sync(0xffffffffu, p3, s1, 4);
                af[1] = (t & 1) ? z1 : z0;
                af[3] = (t & 1) ? w1 : w0;
            }
            #pragma unroll
            for (int dc = 0; dc < 12; dc++) {
                uint32_t bf[2];
                bf[0] = sVu[(kc * 8 + t)     * KVPAD + dc * 8 + g];
                bf[1] = sVu[(kc * 8 + t + 4) * KVPAD + dc * 8 + g];
                mma_tf32(oacc[dc], af, bf);
            }
        }
    }

    // ---- epilogue: ctx = tf32r((O / l) * SCALING), plain e layout ----
    const float inv0 = SCALING / l0;
    const float inv1 = SCALING / l1;
    float* dst0 = g_ctx + ((size_t)b * NN + (q0 + r0)) * EE + h * DD;
    float* dst1 = g_ctx + ((size_t)b * NN + (q0 + r1)) * EE + h * DD;
    #pragma unroll
    for (int dc = 0; dc < 12; dc++) {
        float2 o0, o1;
        o0.x = __uint_as_float(tf32r(oacc[dc][0] * inv0));
        o0.y = __uint_as_float(tf32r(oacc[dc][1] * inv0));
        o1.x = __uint_as_float(tf32r(oacc[dc][2] * inv1));
        o1.y = __uint_as_float(tf32r(oacc[dc][3] * inv1));
        *(float2*)(dst0 + dc * 8 + 2 * t) = o0;
        *(float2*)(dst1 + dc * 8 + 2 * t) = o1;
    }
}

// ---------------------------------------------------------------------------
extern "C" void kernel_launch(void* const* d_in, const int* in_sizes, int n_in,
                              void* d_out, int out_size)
{
    const float* x     = (const float*)d_in[0];
    const float* Wqkv  = (const float*)d_in[1];
    const float* bqkv  = (const float*)d_in[2];
    const float* Wproj = (const float*)d_in[3];
    const float* bproj = (const float*)d_in[4];
    float* out = (float*)d_out;

    cudaFuncSetAttribute(gemm_tc<1>,
                         cudaFuncAttributeMaxDynamicSharedMemorySize, GSMEM);
    cudaFuncSetAttribute(gemm_tc<0>,
                         cudaFuncAttributeMaxDynamicSharedMemorySize, GSMEM);
    cudaFuncSetAttribute(attn_mma,
                         cudaFuncAttributeMaxDynamicSharedMemorySize, ASMEM);

    // pre-pass: round (+permute/transpose) operands
    round_perm_x<<<(1572864 + 255) / 256, 256>>>((const float4*)x, 1572864);
    transpose_round<1><<<dim3(2304 / 32, 768 / 32), dim3(32, 8)>>>(Wqkv, 2304, 1);
    transpose_round<0><<<dim3(768 / 32, 768 / 32), dim3(32, 8)>>>(Wproj, 768, 0);

    dim3 g1(2304 / 128, 8192 / 128);      // 18 x 64
    gemm_tc<1><<<g1, 256, GSMEM>>>(bqkv, nullptr);

    dim3 g2(NN / 128, BB * HH);           // 16 x 32
    attn_mma<<<g2, 256, ASMEM>>>();

    dim3 g3(768 / 128, 8192 / 128);       // 6 x 64
    gemm_tc<0><<<g3, 256, GSMEM>>>(bproj, out);
}

// round 9
// speedup vs baseline: 4.4390x; 1.0854x over previous
#include <cuda_runtime.h>
#include <cstdint>
#include <math.h>

// Problem constants
#define BB 4
#define NN 2048
#define EE 768
#define HH 8
#define DD 96
#define SCALING 0.1020620726159658f   // 96^-0.5

// Scratch (static device globals; no allocation). All tf32-pre-rounded.
// g_Q/g_K use the within-8 d permutation d'=(d&3)*2+(d>>2) (uint2 frag loads).
__device__ float g_Q[BB * HH * NN * DD];    // [b][h][n][d'] permuted
__device__ float g_K[BB * HH * NN * DD];    // [b][h][n][d'] permuted
__device__ float g_V[BB * HH * NN * DD];    // [b][h][n][d]  plain
__device__ float g_ctx[BB * NN * EE];       // [b][n][e]
__device__ float g_xr[BB * NN * EE];        // rounded x (plain)
__device__ float g_Wqkvr[EE * 3 * EE];      // rounded Wqkv [768][2304] (plain)
__device__ float g_Wprojr[EE * EE];         // rounded Wproj [768][768] (plain)

// ---------------------------------------------------------------------------
// helpers
// ---------------------------------------------------------------------------
__device__ __forceinline__ uint32_t tf32r(float x) {
    uint32_t y;
    asm("cvt.rna.tf32.f32 %0, %1;" : "=r"(y) : "f"(x));
    return y;
}

__device__ __forceinline__ int perm8(int k) {           // within-8 permutation
    return (k & ~7) | (((k & 3) << 1) | ((k >> 2) & 1));
}

__device__ __forceinline__ void mma_tf32(float* c, const uint32_t* a,
                                         const uint32_t* b) {
    asm volatile(
        "mma.sync.aligned.m16n8k8.row.col.f32.tf32.tf32.f32 "
        "{%0,%1,%2,%3}, {%4,%5,%6,%7}, {%8,%9}, {%0,%1,%2,%3};\n"
        : "+f"(c[0]), "+f"(c[1]), "+f"(c[2]), "+f"(c[3])
        : "r"(a[0]), "r"(a[1]), "r"(a[2]), "r"(a[3]), "r"(b[0]), "r"(b[1]));
}

__device__ __forceinline__ void cp16(void* smem_ptr, const void* gptr) {
    uint32_t sa = (uint32_t)__cvta_generic_to_shared(smem_ptr);
    asm volatile("cp.async.cg.shared.global [%0], [%1], 16;"
                 :: "r"(sa), "l"(gptr));
}
#define CP_COMMIT() asm volatile("cp.async.commit_group;" ::: "memory")
#define CP_WAIT0()  asm volatile("cp.async.wait_group 0;" ::: "memory")

// ---------------------------------------------------------------------------
// Kernel 0: tf32-round inputs into device scratch (dst resolved device-side)
// ---------------------------------------------------------------------------
__global__ void round_into(const float4* __restrict__ src, int n4, int sel)
{
    float4* dst = (sel == 0) ? (float4*)g_xr
               : (sel == 1) ? (float4*)g_Wqkvr
                            : (float4*)g_Wprojr;
    int i = blockIdx.x * blockDim.x + threadIdx.x;
    if (i < n4) {
        float4 v = src[i];
        v.x = __uint_as_float(tf32r(v.x));
        v.y = __uint_as_float(tf32r(v.y));
        v.z = __uint_as_float(tf32r(v.z));
        v.w = __uint_as_float(tf32r(v.w));
        dst[i] = v;
    }
}

// ---------------------------------------------------------------------------
// Tensor-core tf32 GEMM (R7 shape, measured fastest): cp.async double-buffer.
// C[8192,LDW] = A[8192,768] @ W[768,LDW] + bias. Tile 128x128x32, 8 warps.
// MODE 1 (qkv): A=g_xr, W=g_Wqkvr; scatter to g_Q/g_K (permuted d), g_V.
// MODE 0 (proj): A=g_ctx, W=g_Wprojr; write fp32 out.
// ---------------------------------------------------------------------------
#define APAD 36
#define BPAD 136
#define ASZ (128 * APAD)
#define BSZ (32 * BPAD)
#define GSTG (ASZ + BSZ)
#define GSMEM (2 * GSTG * 4)

template<int MODE, int LDW>
__global__ __launch_bounds__(256, 2) void gemm_tc(
    const float* __restrict__ bias,
    float* __restrict__ out)
{
    extern __shared__ float sm[];
    const float* A = (MODE == 0) ? (const float*)g_ctx : (const float*)g_xr;
    const float* W = (MODE == 0) ? (const float*)g_Wprojr : (const float*)g_Wqkvr;

    const int tid  = threadIdx.x;
    const int lane = tid & 31;
    const int wid  = tid >> 5;
    const int wm   = wid & 3;
    const int wn   = wid >> 2;
    const int row0 = blockIdx.y * 128;
    const int col0 = blockIdx.x * 128;
    const int g    = lane >> 2;
    const int t    = lane & 3;

    float acc[2][8][4];
    #pragma unroll
    for (int ml = 0; ml < 2; ml++)
        #pragma unroll
        for (int nl = 0; nl < 8; nl++)
            #pragma unroll
            for (int e = 0; e < 4; e++) acc[ml][nl][e] = 0.f;

    auto issue = [&](int kt, int s) {
        float* sA = sm + s * GSTG;
        float* sB = sA + ASZ;
        #pragma unroll
        for (int p = 0; p < 4; p++) {
            int i = tid + p * 256;
            int m = i >> 3, k4 = i & 7;
            cp16(sA + m * APAD + k4 * 4,
                 A + (size_t)(row0 + m) * 768 + kt * 32 + k4 * 4);
        }
        #pragma unroll
        for (int p = 0; p < 4; p++) {
            int i = tid + p * 256;
            int k = i >> 5, n4 = i & 31;
            cp16(sB + k * BPAD + n4 * 4,
                 W + (size_t)(kt * 32 + k) * LDW + col0 + n4 * 4);
        }
        CP_COMMIT();
    };

    issue(0, 0);

    #pragma unroll 1
    for (int kt = 0; kt < 24; kt++) {
        const int s = kt & 1;
        CP_WAIT0();
        __syncthreads();
        if (kt < 23) issue(kt + 1, s ^ 1);

        const uint32_t* sA = (const uint32_t*)(sm + s * GSTG);
        const uint32_t* sB = sA + ASZ;

        #pragma unroll
        for (int ks = 0; ks < 4; ks++) {
            const int k0 = ks * 8;
            uint32_t af[2][4];
            #pragma unroll
            for (int ml = 0; ml < 2; ml++) {
                const int m_off = wm * 32 + ml * 16;
                af[ml][0] = sA[(m_off + g)     * APAD + k0 + t];
                af[ml][1] = sA[(m_off + g + 8) * APAD + k0 + t];
                af[ml][2] = sA[(m_off + g)     * APAD + k0 + t + 4];
                af[ml][3] = sA[(m_off + g + 8) * APAD + k0 + t + 4];
            }
            #pragma unroll
            for (int nl = 0; nl < 8; nl++) {
                const int n_off = wn * 64 + nl * 8;
                uint32_t bf[2];
                bf[0] = sB[(k0 + t)     * BPAD + n_off + g];
                bf[1] = sB[(k0 + t + 4) * BPAD + n_off + g];
                mma_tf32(acc[0][nl], af[0], bf);
                mma_tf32(acc[1][nl], af[1], bf);
            }
        }
    }

    // ---- epilogue ----
    if (MODE == 0) {
        #pragma unroll
        for (int ml = 0; ml < 2; ml++) {
            #pragma unroll
            for (int rh = 0; rh < 2; rh++) {
                int m = row0 + wm * 32 + ml * 16 + g + rh * 8;
                float* op = out + (size_t)m * LDW;
                #pragma unroll
                for (int nl = 0; nl < 8; nl++) {
                    int c = col0 + wn * 64 + nl * 8 + 2 * t;
                    float2 bv = *(const float2*)(bias + c);
                    float2 o;
                    o.x = acc[ml][nl][rh * 2 + 0] + bv.x;
                    o.y = acc[ml][nl][rh * 2 + 1] + bv.y;
                    *(float2*)(op + c) = o;
                }
            }
        }
    } else {
        #pragma unroll
        for (int ml = 0; ml < 2; ml++) {
            #pragma unroll
            for (int rh = 0; rh < 2; rh++) {
                int m = row0 + wm * 32 + ml * 16 + g + rh * 8;
                int b = m >> 11, n = m & 2047;
                #pragma unroll
                for (int nl = 0; nl < 8; nl++) {
                    #pragma unroll
                    for (int e = 0; e < 2; e++) {
                        int c = col0 + wn * 64 + nl * 8 + 2 * t + e;
                        float v = acc[ml][nl][rh * 2 + e] + __ldg(bias + c);
                        int sel = c % 3;
                        int hd  = c / 3;
                        int h   = hd / 96;
                        int d   = hd - h * 96;
                        float vr = __uint_as_float(tf32r(v));
                        size_t rowo = ((size_t)(b * HH + h) * NN + n) * DD;
                        if (sel == 0)      g_Q[rowo + perm8(d)] = vr;
                        else if (sel == 1) g_K[rowo + perm8(d)] = vr;
                        else               g_V[rowo + d]        = vr;
                    }
                }
            }
        }
    }
}

// ---------------------------------------------------------------------------
// Flash attention on mma.sync tf32, BN=64 keys/tile (32 tiles), cp.async
// double-buffered K/V. BM=128 (8 warps x 16 rows -> warp-local softmax).
// g_Q/g_K permuted d -> uint2 fragment loads; V plain scalar frags.
// Pad 104 keeps all frag LDS conflict-free. SCALING post-normalization.
// ---------------------------------------------------------------------------
#define KVPAD 104
#define KVSZ (64 * KVPAD)          // 6656 floats per tensor
#define ASTG (2 * KVSZ)            // K+V per stage
#define ASMEM (2 * ASTG * 4)       // 106496 B

__global__ __launch_bounds__(256) void attn_mma()
{
    extern __shared__ float sm[];

    const int tid  = threadIdx.x;
    const int lane = tid & 31;
    const int wid  = tid >> 5;
    const int g    = lane >> 2;
    const int t    = lane & 3;
    const int q0   = blockIdx.x * 128;
    const int bh   = blockIdx.y;
    const int b    = bh >> 3;
    const int h    = bh & 7;

    const float* Qg = g_Q + (size_t)bh * NN * DD;
    const float* Kg = g_K + (size_t)bh * NN * DD;
    const float* Vg = g_V + (size_t)bh * NN * DD;

    const int r0 = 16 * wid + g;
    const int r1 = r0 + 8;

    auto issueKV = [&](int kt, int s) {
        const int j0 = kt * 64;
        float* bK = sm + s * ASTG;
        float* bV = bK + KVSZ;
        #pragma unroll
        for (int p = 0; p < 6; p++) {
            int i  = tid + p * 256;              // 1536 float4s per tensor
            int r  = i / 24, c4 = i % 24;
            cp16(bK + r * KVPAD + c4 * 4, Kg + (size_t)(j0 + r) * DD + c4 * 4);
            cp16(bV + r * KVPAD + c4 * 4, Vg + (size_t)(j0 + r) * DD + c4 * 4);
        }
        CP_COMMIT();
    };

    issueKV(0, 0);

    // Q fragments register-resident: permuted storage -> uint2 per pair
    uint32_t qf[12][4];
    {
        const uint32_t* Q0 = (const uint32_t*)(Qg + (size_t)(q0 + r0) * DD);
        const uint32_t* Q1 = (const uint32_t*)(Qg + (size_t)(q0 + r1) * DD);
        #pragma unroll
        for (int c = 0; c < 12; c++) {
            uint2 v0 = *(const uint2*)&Q0[8 * c + 2 * t];
            uint2 v1 = *(const uint2*)&Q1[8 * c + 2 * t];
            qf[c][0] = v0.x; qf[c][2] = v0.y;
            qf[c][1] = v1.x; qf[c][3] = v1.y;
        }
    }

    float m0 = -1e30f, m1 = -1e30f, l0 = 0.f, l1 = 0.f;
    float oacc[12][4];
    #pragma unroll
    for (int dc = 0; dc < 12; dc++)
        #pragma unroll
        for (int e = 0; e < 4; e++) oacc[dc][e] = 0.f;

    #pragma unroll 1
    for (int kt = 0; kt < 32; kt++) {
        const int s = kt & 1;
        CP_WAIT0();
        __syncthreads();
        if (kt < 31) issueKV(kt + 1, s ^ 1);

        const uint32_t* sKu = (const uint32_t*)(sm + s * ASTG);
        const uint32_t* sVu = sKu + KVSZ;

        // ---- S = Q K^T : 8 n-chunks x 12 k-chunks ----
        float sacc[8][4];
        #pragma unroll
        for (int nc = 0; nc < 8; nc++)
            #pragma unroll
            for (int e = 0; e < 4; e++) sacc[nc][e] = 0.f;

        #pragma unroll
        for (int kc = 0; kc < 12; kc++) {
            #pragma unroll
            for (int nc = 0; nc < 8; nc++) {
                uint2 v = *(const uint2*)&sKu[(nc * 8 + g) * KVPAD + kc * 8 + 2 * t];
                uint32_t bf[2] = { v.x, v.y };
                mma_tf32(sacc[nc], qf[kc], bf);
            }
        }

        // ---- online softmax ----
        float lm0 = sacc[0][0], lm1 = sacc[0][2];
        #pragma unroll
        for (int nc = 0; nc < 8; nc++) {
            lm0 = fmaxf(lm0, fmaxf(sacc[nc][0], sacc[nc][1]));
            lm1 = fmaxf(lm1, fmaxf(sacc[nc][2], sacc[nc][3]));
        }
        lm0 = fmaxf(lm0, __shfl_xor_sync(0xffffffffu, lm0, 1));
        lm0 = fmaxf(lm0, __shfl_xor_sync(0xffffffffu, lm0, 2));
        lm1 = fmaxf(lm1, __shfl_xor_sync(0xffffffffu, lm1, 1));
        lm1 = fmaxf(lm1, __shfl_xor_sync(0xffffffffu, lm1, 2));

        const float mn0 = fmaxf(m0, lm0);
        const float mn1 = fmaxf(m1, lm1);
        const float sc0 = __expf(m0 - mn0);
        const float sc1 = __expf(m1 - mn1);
        m0 = mn0; m1 = mn1;

        float rs0 = 0.f, rs1 = 0.f;
        #pragma unroll
        for (int nc = 0; nc < 8; nc++) {
            sacc[nc][0] = __expf(sacc[nc][0] - mn0);
            sacc[nc][1] = __expf(sacc[nc][1] - mn0);
            sacc[nc][2] = __expf(sacc[nc][2] - mn1);
            sacc[nc][3] = __expf(sacc[nc][3] - mn1);
            rs0 += sacc[nc][0] + sacc[nc][1];
            rs1 += sacc[nc][2] + sacc[nc][3];
        }
        rs0 += __shfl_xor_sync(0xffffffffu, rs0, 1);
        rs0 += __shfl_xor_sync(0xffffffffu, rs0, 2);
        rs1 += __shfl_xor_sync(0xffffffffu, rs1, 1);
        rs1 += __shfl_xor_sync(0xffffffffu, rs1, 2);
        l0 = l0 * sc0 + rs0;
        l1 = l1 * sc1 + rs1;

        if (__any_sync(0xffffffffu, (sc0 != 1.f) || (sc1 != 1.f))) {
            #pragma unroll
            for (int dc = 0; dc < 12; dc++) {
                oacc[dc][0] *= sc0; oacc[dc][1] *= sc0;
                oacc[dc][2] *= sc1; oacc[dc][3] *= sc1;
            }
        }

        // ---- O += P @ V : 8 kc x 12 dc ----
        const int s0 = t >> 1;
        const int s1 = s0 + 2;
        #pragma unroll
        for (int kc = 0; kc < 8; kc++) {
            uint32_t p0 = tf32r(sacc[kc][0]);
            uint32_t p1 = tf32r(sacc[kc][1]);
            uint32_t p2 = tf32r(sacc[kc][2]);
            uint32_t p3 = tf32r(sacc[kc][3]);
            uint32_t af[4];
            {
                uint32_t x0 = __shfl_sync(0xffffffffu, p0, s0, 4);
                uint32_t x1 = __shfl_sync(0xffffffffu, p1, s0, 4);
                uint32_t y0 = __shfl_sync(0xffffffffu, p0, s1, 4);
                uint32_t y1 = __shfl_sync(0xffffffffu, p1, s1, 4);
                af[0] = (t & 1) ? x1 : x0;
                af[2] = (t & 1) ? y1 : y0;
                uint32_t z0 = __shfl_sync(0xffffffffu, p2, s0, 4);
                uint32_t z1 = __shfl_sync(0xffffffffu, p3, s0, 4);
                uint32_t w0 = __shfl_sync(0xffffffffu, p2, s1, 4);
                uint32_t w1 = __shfl_sync(0xffffffffu, p3, s1, 4);
                af[1] = (t & 1) ? z1 : z0;
                af[3] = (t & 1) ? w1 : w0;
            }
            #pragma unroll
            for (int dc = 0; dc < 12; dc++) {
                uint32_t bf[2];
                bf[0] = sVu[(kc * 8 + t)     * KVPAD + dc * 8 + g];
                bf[1] = sVu[(kc * 8 + t + 4) * KVPAD + dc * 8 + g];
                mma_tf32(oacc[dc], af, bf);
            }
        }
    }

    // ---- epilogue: ctx = tf32r((O / l) * SCALING), plain e layout ----
    const float inv0 = SCALING / l0;
    const float inv1 = SCALING / l1;
    float* dst0 = g_ctx + ((size_t)b * NN + (q0 + r0)) * EE + h * DD;
    float* dst1 = g_ctx + ((size_t)b * NN + (q0 + r1)) * EE + h * DD;
    #pragma unroll
    for (int dc = 0; dc < 12; dc++) {
        float2 o0, o1;
        o0.x = __uint_as_float(tf32r(oacc[dc][0] * inv0));
        o0.y = __uint_as_float(tf32r(oacc[dc][1] * inv0));
        o1.x = __uint_as_float(tf32r(oacc[dc][2] * inv1));
        o1.y = __uint_as_float(tf32r(oacc[dc][3] * inv1));
        *(float2*)(dst0 + dc * 8 + 2 * t) = o0;
        *(float2*)(dst1 + dc * 8 + 2 * t) = o1;
    }
}

// ---------------------------------------------------------------------------
extern "C" void kernel_launch(void* const* d_in, const int* in_sizes, int n_in,
                              void* d_out, int out_size)
{
    const float* x     = (const float*)d_in[0];
    const float* Wqkv  = (const float*)d_in[1];
    const float* bqkv  = (const float*)d_in[2];
    const float* Wproj = (const float*)d_in[3];
    const float* bproj = (const float*)d_in[4];
    float* out = (float*)d_out;

    cudaFuncSetAttribute(gemm_tc<1, 2304>,
                         cudaFuncAttributeMaxDynamicSharedMemorySize, GSMEM);
    cudaFuncSetAttribute(gemm_tc<0, 768>,
                         cudaFuncAttributeMaxDynamicSharedMemorySize, GSMEM);
    cudaFuncSetAttribute(attn_mma,
                         cudaFuncAttributeMaxDynamicSharedMemorySize, ASMEM);

    // pre-round inputs (tf32 RNA)
    round_into<<<(1572864 + 255) / 256, 256>>>((const float4*)x,     1572864, 0);
    round_into<<<(442368  + 255) / 256, 256>>>((const float4*)Wqkv,  442368,  1);
    round_into<<<(147456  + 255) / 256, 256>>>((const float4*)Wproj, 147456,  2);

    dim3 g1(2304 / 128, 8192 / 128);      // 18 x 64
    gemm_tc<1, 2304><<<g1, 256, GSMEM>>>(bqkv, nullptr);

    dim3 g2(NN / 128, BB * HH);           // 16 x 32
    attn_mma<<<g2, 256, ASMEM>>>();

    dim3 g3(768 / 128, 8192 / 128);       // 6 x 64
    gemm_tc<0, 768><<<g3, 256, GSMEM>>>(bproj, out);
}